// round 13
// baseline (speedup 1.0000x reference)
#include <cuda_runtime.h>
#include <cuda_bf16.h>
#include <math.h>
#include <stdint.h>

#define N_NODES 50000
#define FDIM    200
#define E1C     400000
#define E2C     100000
#define E_TOT   500000
#define ALPHA   0.2f

// tensor-GEMM tiling (bf16 3x split, K pairs), 512 threads / 16 warps
#define BM 128
#define KP_TILE 20
#define NKB 5
#define A_STRIDE 20
#define B_STRIDE 200
#define A_BUFU (BM * A_STRIDE)
#define B_BUFU (KP_TILE * B_STRIDE + 64)
#define SMEM_UINTS (4 * A_BUFU + 4 * B_BUFU)
#define SMEM_BYTES (SMEM_UINTS * 4)
#define TG_THREADS 512

// ---- device scratch ----
__device__ float g_X1[(size_t)N_NODES * FDIM];
__device__ float g_X2[(size_t)N_NODES * FDIM];
__device__ float g_ACC[(size_t)N_NODES * FDIM];
__device__ float g_rs[N_NODES];
__device__ float g_p[4 * N_NODES];
__device__ float g_v[600];
__device__ float g_w[600];
__device__ unsigned g_bqh[300 * FDIM];
__device__ unsigned g_bql[300 * FDIM];
__device__ unsigned g_xqh[(size_t)N_NODES * 100];
__device__ unsigned g_xql[(size_t)N_NODES * 100];
__device__ unsigned g_gqh[(size_t)N_NODES * 100];
__device__ unsigned g_gql[(size_t)N_NODES * 100];
__device__ int  g_deg[N_NODES];          // zero-initialized at load; scan re-zeroes each run
__device__ int  g_off[N_NODES + 1];
__device__ int  g_cur[N_NODES];
__device__ int2 g_rec[E_TOT];

__device__ __forceinline__ float dot4(float4 a, float4 b) {
    return a.x * b.x + a.y * b.y + a.z * b.z + a.w * b.w;
}

__device__ __forceinline__ float tanh_fast(float x) {
    float y;
    asm("tanh.approx.f32 %0, %1;" : "=f"(y) : "f"(x));
    return y;
}

__device__ __forceinline__ void split_pack2(float f0, float f1,
                                            unsigned& hi, unsigned& lo) {
    __nv_bfloat162 h = __float22bfloat162_rn(make_float2(f0, f1));
    hi = *reinterpret_cast<unsigned*>(&h);
    float l0 = f0 - __bfloat162float(h.x);
    float l1 = f1 - __bfloat162float(h.y);
    __nv_bfloat162 l = __float22bfloat162_rn(make_float2(l0, l1));
    lo = *reinterpret_cast<unsigned*>(&l);
}

__device__ __forceinline__ void mma_bf16_k16(float* c, const unsigned* a,
                                             unsigned b0, unsigned b1) {
    asm volatile("mma.sync.aligned.m16n8k16.row.col.f32.bf16.bf16.f32 "
                 "{%0,%1,%2,%3}, {%4,%5,%6,%7}, {%8,%9}, {%0,%1,%2,%3};"
                 : "+f"(c[0]), "+f"(c[1]), "+f"(c[2]), "+f"(c[3])
                 : "r"(a[0]), "r"(a[1]), "r"(a[2]), "r"(a[3]), "r"(b0), "r"(b1));
}

__device__ __forceinline__ void mma_bf16_k8(float* c, unsigned a0, unsigned a1,
                                            unsigned b0) {
    asm volatile("mma.sync.aligned.m16n8k8.row.col.f32.bf16.bf16.f32 "
                 "{%0,%1,%2,%3}, {%4,%5}, {%6}, {%0,%1,%2,%3};"
                 : "+f"(c[0]), "+f"(c[1]), "+f"(c[2]), "+f"(c[3])
                 : "r"(a0), "r"(a1), "r"(b0));
}

__device__ __forceinline__ void cp_async16(void* smem_dst, const void* gmem_src, bool pred) {
    uint32_t s = (uint32_t)__cvta_generic_to_shared(smem_dst);
    int sz = pred ? 16 : 0;
    asm volatile("cp.async.cg.shared.global [%0], [%1], 16, %2;"
                 :: "r"(s), "l"(gmem_src), "r"(sz));
}
__device__ __forceinline__ void cp_commit() {
    asm volatile("cp.async.commit_group;");
}
template<int N>
__device__ __forceinline__ void cp_wait() {
    asm volatile("cp.async.wait_group %0;" :: "n"(N));
}

// ---------------- CSR build ----------------
__global__ __launch_bounds__(256) void deg_kernel(const int* __restrict__ edge,
                                                  const int* __restrict__ edge2) {
    int e = blockIdx.x * blockDim.x + threadIdx.x;
    if (e >= E_TOT) return;
    int src = (e < E1C) ? edge[e] : edge2[e - E1C];
    atomicAdd(&g_deg[src], 1);
}

__global__ __launch_bounds__(1024) void scan_kernel() {
    __shared__ int warp_sums[32];
    __shared__ int s_total;
    __shared__ int s_run;
    int t = threadIdx.x;
    int lane = t & 31, wid = t >> 5;
    if (t == 0) s_run = 0;
    __syncthreads();
    for (int base = 0; base < N_NODES; base += 1024) {
        int idx = base + t;
        int v = 0;
        if (idx < N_NODES) {
            v = g_deg[idx];
            g_deg[idx] = 0;   // re-zero for next graph replay
        }
        int incl = v;
        #pragma unroll
        for (int d = 1; d < 32; d <<= 1) {
            int n = __shfl_up_sync(0xffffffffu, incl, d);
            if (lane >= d) incl += n;
        }
        if (lane == 31) warp_sums[wid] = incl;
        __syncthreads();
        if (wid == 0) {
            int ws = warp_sums[lane];
            int wincl = ws;
            #pragma unroll
            for (int d = 1; d < 32; d <<= 1) {
                int n = __shfl_up_sync(0xffffffffu, wincl, d);
                if (lane >= d) wincl += n;
            }
            warp_sums[lane] = wincl - ws;
            if (lane == 31) s_total = wincl;
        }
        __syncthreads();
        int excl = s_run + warp_sums[wid] + incl - v;
        if (idx < N_NODES) { g_off[idx] = excl; g_cur[idx] = excl; }
        __syncthreads();
        if (t == 0) s_run += s_total;
        __syncthreads();
    }
    if (t == 0) g_off[N_NODES] = s_run;
}

__global__ __launch_bounds__(256) void fill_kernel(const int* __restrict__ edge,
                                                   const int* __restrict__ edge2) {
    int e = blockIdx.x * blockDim.x + threadIdx.x;
    if (e >= E_TOT) return;
    int src, dst;
    if (e < E1C) { src = edge[e]; dst = edge[E1C + e]; }
    else         { src = edge2[e - E1C]; dst = edge2[E2C + (e - E1C)]; }
    int pos = atomicAdd(&g_cur[src], 1);
    g_rec[pos] = make_int2(dst, e);
}

// ---------------- weights prep ----------------
__global__ __launch_bounds__(256) void transpose_kernel(const float* __restrict__ a) {
    int i = blockIdx.x * blockDim.x + threadIdx.x;
    if (i >= 300 * FDIM) return;
    int jp = i / FDIM;
    int n  = i % FDIM;
    float f0 = a[n * 600 + 2 * jp];
    float f1 = a[n * 600 + 2 * jp + 1];
    unsigned hi, lo;
    split_pack2(f0, f1, hi, lo);
    g_bqh[i] = hi;
    g_bql[i] = lo;
}

__global__ __launch_bounds__(256) void pack_x_kernel(const float* __restrict__ x) {
    int i = blockIdx.x * blockDim.x + threadIdx.x;
    if (i >= N_NODES * 50) return;
    int m = i / 50, c = i % 50;
    float4 v = ((const float4*)x)[i];
    unsigned h0, l0, h1, l1;
    split_pack2(v.x, v.y, h0, l0);
    split_pack2(v.z, v.w, h1, l1);
    size_t o = (size_t)m * 100 + 2 * c;
    *(uint2*)&g_xqh[o] = make_uint2(h0, h1);
    *(uint2*)&g_xql[o] = make_uint2(l0, l1);
}

__global__ __launch_bounds__(640) void vw_kernel(const float* __restrict__ a,
                                                 const float* __restrict__ a2,
                                                 const float* __restrict__ mw) {
    int j = threadIdx.x;
    if (j >= 600) return;
    float v = 0.f, w = 0.f;
    for (int o = 0; o < FDIM; o++) {
        float aj = a[o * 600 + j];
        v += aj * a2[o];
        w += aj * mw[o];
    }
    g_v[j] = v;
    g_w[j] = w;
}

__global__ __launch_bounds__(256) void pvec_kernel(const float* __restrict__ x) {
    __shared__ float4 sv[100];
    __shared__ float4 sw[100];
    int t = threadIdx.x;
    if (t < 100)       sv[t]       = ((const float4*)g_v)[t];
    else if (t < 200)  sw[t - 100] = ((const float4*)g_w)[t - 100];
    __syncthreads();

    int warp = t >> 5, lane = t & 31;
    int node = blockIdx.x * 8 + warp;
    if (node >= N_NODES) return;

    const float4* xr = (const float4*)x + (size_t)node * 50;
    float4 x0 = xr[lane];
    float4 x1 = (lane < 18) ? xr[32 + lane] : make_float4(0, 0, 0, 0);

    float p1  = dot4(x0, sv[lane])      + ((lane < 18) ? dot4(x1, sv[32 + lane]) : 0.f);
    float p2  = dot4(x0, sv[50 + lane]) + ((lane < 18) ? dot4(x1, sv[82 + lane]) : 0.f);
    float pm1 = dot4(x0, sw[lane])      + ((lane < 18) ? dot4(x1, sw[32 + lane]) : 0.f);
    float pm2 = dot4(x0, sw[50 + lane]) + ((lane < 18) ? dot4(x1, sw[82 + lane]) : 0.f);

    #pragma unroll
    for (int off = 16; off; off >>= 1) {
        p1  += __shfl_xor_sync(0xffffffffu, p1, off);
        p2  += __shfl_xor_sync(0xffffffffu, p2, off);
        pm1 += __shfl_xor_sync(0xffffffffu, pm1, off);
        pm2 += __shfl_xor_sync(0xffffffffu, pm2, off);
    }
    if (lane == 0) {
        g_p[node]               = p1;
        g_p[N_NODES + node]     = p2;
        g_p[2 * N_NODES + node] = pm1;
        g_p[3 * N_NODES + node] = pm2;
    }
}

// ---------------- bf16 3x tensor-core GEMM (512 threads, 4mg x 4ng) ----------------
__device__ __forceinline__ void stage_tile(unsigned* Ah, unsigned* Al,
                                           unsigned* Bh, unsigned* Bl,
                                           const unsigned* gAh, const unsigned* gAl,
                                           int M, int row0, int jp0, int kb, int t) {
    int kp0 = kb * KP_TILE;
    #pragma unroll
    for (int i = 0; i < 2; i++) {
        int idx = t + i * TG_THREADS;
        if (idx < 640) {
            int r = idx / 5, c4 = idx % 5;
            bool ok = (row0 + r) < M;
            size_t go = (size_t)(row0 + r) * 100 + kp0 + c4 * 4;
            cp_async16(Ah + r * A_STRIDE + c4 * 4, gAh + go, ok);
            cp_async16(Al + r * A_STRIDE + c4 * 4, gAl + go, ok);
        }
    }
    const unsigned* sH = g_bqh + (size_t)(jp0 + kp0) * FDIM;
    const unsigned* sL = g_bql + (size_t)(jp0 + kp0) * FDIM;
    #pragma unroll
    for (int i = 0; i < 2; i++) {
        int idx = t + i * TG_THREADS;
        if (idx < 1000) {
            int row = idx / 50, c4 = idx % 50;
            cp_async16(Bh + row * B_STRIDE + c4 * 4, sH + idx * 4, true);
            cp_async16(Bl + row * B_STRIDE + c4 * 4, sL + idx * 4, true);
        }
    }
}

// dest 0 -> g_X1, 1 -> g_X2, 2 -> final epilogue into fout
__global__ void __launch_bounds__(TG_THREADS, 1)
tgemm_kernel(const unsigned* __restrict__ gAh, const unsigned* __restrict__ gAl,
             int M, int jp0, int dest, float* __restrict__ fout) {
    extern __shared__ unsigned smu_[];
    unsigned* Ah[2] = { smu_, smu_ + A_BUFU };
    unsigned* Al[2] = { smu_ + 2 * A_BUFU, smu_ + 3 * A_BUFU };
    unsigned* Bh[2] = { smu_ + 4 * A_BUFU, smu_ + 4 * A_BUFU + B_BUFU };
    unsigned* Bl[2] = { smu_ + 4 * A_BUFU + 2 * B_BUFU, smu_ + 4 * A_BUFU + 3 * B_BUFU };

    int row0 = blockIdx.x * BM;
    int t = threadIdx.x;
    int warp = t >> 5, lane = t & 31;
    int mg = warp >> 2;
    int ng = warp & 3;
    int n0 = ng * 56;
    int m0w = mg * 32;
    int lr = lane >> 2;
    int lc = lane & 3;

    float acc[2][7][4];
    #pragma unroll
    for (int a_ = 0; a_ < 2; a_++)
        #pragma unroll
        for (int b_ = 0; b_ < 7; b_++)
            #pragma unroll
            for (int c_ = 0; c_ < 4; c_++) acc[a_][b_][c_] = 0.f;

    stage_tile(Ah[0], Al[0], Bh[0], Bl[0], gAh, gAl, M, row0, jp0, 0, t);
    cp_commit();

    for (int kb = 0; kb < NKB; kb++) {
        int cur = kb & 1;
        if (kb + 1 < NKB) {
            stage_tile(Ah[cur ^ 1], Al[cur ^ 1], Bh[cur ^ 1], Bl[cur ^ 1],
                       gAh, gAl, M, row0, jp0, kb + 1, t);
            cp_commit();
            cp_wait<1>();
        } else {
            cp_wait<0>();
        }
        __syncthreads();

        const unsigned* Ach = Ah[cur];
        const unsigned* Acl = Al[cur];
        const unsigned* Bch = Bh[cur];
        const unsigned* Bcl = Bl[cur];

        #pragma unroll
        for (int st = 0; st < 2; st++) {
            int kpb = st * 8;
            unsigned ah[2][4], al[2][4];
            #pragma unroll
            for (int mt = 0; mt < 2; mt++) {
                int mrow = m0w + mt * 16 + lr;
                ah[mt][0] = Ach[mrow * A_STRIDE + kpb + lc];
                ah[mt][1] = Ach[(mrow + 8) * A_STRIDE + kpb + lc];
                ah[mt][2] = Ach[mrow * A_STRIDE + kpb + lc + 4];
                ah[mt][3] = Ach[(mrow + 8) * A_STRIDE + kpb + lc + 4];
                al[mt][0] = Acl[mrow * A_STRIDE + kpb + lc];
                al[mt][1] = Acl[(mrow + 8) * A_STRIDE + kpb + lc];
                al[mt][2] = Acl[mrow * A_STRIDE + kpb + lc + 4];
                al[mt][3] = Acl[(mrow + 8) * A_STRIDE + kpb + lc + 4];
            }
            #pragma unroll
            for (int nt = 0; nt < 7; nt++) {
                int nc = n0 + nt * 8 + lr;
                unsigned bh0 = Bch[(kpb + lc) * B_STRIDE + nc];
                unsigned bh1 = Bch[(kpb + lc + 4) * B_STRIDE + nc];
                unsigned bl0 = Bcl[(kpb + lc) * B_STRIDE + nc];
                unsigned bl1 = Bcl[(kpb + lc + 4) * B_STRIDE + nc];
                #pragma unroll
                for (int mt = 0; mt < 2; mt++) {
                    mma_bf16_k16(acc[mt][nt], ah[mt], bh0, bh1);
                    mma_bf16_k16(acc[mt][nt], ah[mt], bl0, bl1);
                    mma_bf16_k16(acc[mt][nt], al[mt], bh0, bh1);
                }
            }
        }
        {
            unsigned ah8[2][2], al8[2][2];
            #pragma unroll
            for (int mt = 0; mt < 2; mt++) {
                int mrow = m0w + mt * 16 + lr;
                ah8[mt][0] = Ach[mrow * A_STRIDE + 16 + lc];
                ah8[mt][1] = Ach[(mrow + 8) * A_STRIDE + 16 + lc];
                al8[mt][0] = Acl[mrow * A_STRIDE + 16 + lc];
                al8[mt][1] = Acl[(mrow + 8) * A_STRIDE + 16 + lc];
            }
            #pragma unroll
            for (int nt = 0; nt < 7; nt++) {
                int nc = n0 + nt * 8 + lr;
                unsigned bh0 = Bch[(16 + lc) * B_STRIDE + nc];
                unsigned bl0 = Bcl[(16 + lc) * B_STRIDE + nc];
                #pragma unroll
                for (int mt = 0; mt < 2; mt++) {
                    mma_bf16_k8(acc[mt][nt], ah8[mt][0], ah8[mt][1], bh0);
                    mma_bf16_k8(acc[mt][nt], ah8[mt][0], ah8[mt][1], bl0);
                    mma_bf16_k8(acc[mt][nt], al8[mt][0], al8[mt][1], bh0);
                }
            }
        }
        __syncthreads();
    }

    if (dest != 2) {
        float* Out = (dest == 0) ? g_X1 : g_X2;
        #pragma unroll
        for (int mt = 0; mt < 2; mt++) {
            int r0 = row0 + m0w + mt * 16 + lr;
            #pragma unroll
            for (int nt = 0; nt < 7; nt++) {
                int col = n0 + nt * 8 + 2 * lc;
                if (col >= FDIM) continue;
                if (r0 < M)
                    *(float2*)(Out + (size_t)r0 * FDIM + col) =
                        make_float2(acc[mt][nt][0], acc[mt][nt][1]);
                if (r0 + 8 < M)
                    *(float2*)(Out + (size_t)(r0 + 8) * FDIM + col) =
                        make_float2(acc[mt][nt][2], acc[mt][nt][3]);
            }
        }
    } else {
        #pragma unroll
        for (int mt = 0; mt < 2; mt++) {
            #pragma unroll
            for (int h = 0; h < 2; h++) {
                int r = row0 + m0w + mt * 16 + lr + 8 * h;
                if (r >= M) continue;
                float rs = g_rs[r];
                if (rs == 0.f) {
                    #pragma unroll
                    for (int nt = 0; nt < 7; nt++) {
                        int col = n0 + nt * 8 + 2 * lc;
                        if (col >= FDIM) continue;
                        *(float2*)(fout + (size_t)r * FDIM + col) = make_float2(0.f, 0.f);
                    }
                } else {
                    float inv = 1.f / rs;
                    #pragma unroll
                    for (int nt = 0; nt < 7; nt++) {
                        int col = n0 + nt * 8 + 2 * lc;
                        if (col >= FDIM) continue;
                        size_t idx = (size_t)r * FDIM + col;
                        float2 x1 = *(const float2*)(g_X1 + idx);
                        float2 av = *(const float2*)(g_ACC + idx);
                        float g0 = acc[mt][nt][2 * h + 0];
                        float g1 = acc[mt][nt][2 * h + 1];
                        float v0 = x1.x + (av.x + g0) * inv;
                        float v1 = x1.y + (av.y + g1) * inv;
                        v0 = (v0 > 0.f) ? v0 : (expf(v0) - 1.f);
                        v1 = (v1 > 0.f) ? v1 : (expf(v1) - 1.f);
                        *(float2*)(fout + idx) = make_float2(v0, v1);
                    }
                }
            }
        }
    }
}

// ---------------- fused score+gather: warp-pair per node ----------------
// role 0: loads emb, computes edge scores inline, accumulates G + rowsum,
//         publishes ee to smem (double-buffered) per 32-edge batch.
// role 1: waits on per-pair named barrier, accumulates ACC from X2 with ee.
__global__ __launch_bounds__(256) void gather_fused(const float* __restrict__ emb1,
                                                    const float* __restrict__ emb2,
                                                    const float* __restrict__ mlp_b) {
    __shared__ float4 sv[50];
    __shared__ float4 sw[50];
    __shared__ float s_ee[4][2][32];
    int t = threadIdx.x;
    if (t < 50)       sv[t]      = *(const float4*)&g_v[400 + t * 4];
    else if (t < 100) sw[t - 50] = *(const float4*)&g_w[400 + (t - 50) * 4];
    __syncthreads();

    int warp = t >> 5, lane = t & 31;
    int pair = warp >> 1;
    int role = warp & 1;
    int node = blockIdx.x * 4 + pair;
    if (node >= N_NODES) return;
    int barid = pair + 1;

    int beg = g_off[node];
    int end = g_off[node + 1];
    int nb = (end - beg + 31) >> 5;

    float4 a0 = make_float4(0, 0, 0, 0), a1 = a0;
    float rs = 0.f;

    if (role == 0) {
        float p1  = g_p[node];
        float pm1 = g_p[2 * N_NODES + node];
        float bias = mlp_b[0];
        for (int b = 0; b < nb; b++) {
            int base = beg + (b << 5);
            int cnt  = min(32, end - base);
            int2 rec   = (lane < cnt) ? g_rec[base + lane] : make_int2(0, 0);
            float pd2  = (lane < cnt) ? g_p[N_NODES + rec.x] : 0.f;
            float pmd2 = (lane < cnt) ? g_p[3 * N_NODES + rec.x] : 0.f;
            float* eslot = s_ee[pair][b & 1];

            int j = 0;
            for (; j + 4 <= cnt; j += 4) {
                const float4* p[4];
                #pragma unroll
                for (int k = 0; k < 4; k++) {
                    int eid = __shfl_sync(0xffffffffu, rec.y, j + k);
                    p[k] = (eid < E1C) ? (const float4*)emb1 + (size_t)eid * 50
                                       : (const float4*)emb2 + (size_t)(eid - E1C) * 50;
                }
                float4 m0[4], m1[4];
                #pragma unroll
                for (int k = 0; k < 4; k++) m0[k] = p[k][lane];
                #pragma unroll
                for (int k = 0; k < 4; k++)
                    m1[k] = (lane < 18) ? p[k][32 + lane] : make_float4(0, 0, 0, 0);

                float q3[4], qm[4];
                #pragma unroll
                for (int k = 0; k < 4; k++) {
                    q3[k] = dot4(m0[k], sv[lane]) + ((lane < 18) ? dot4(m1[k], sv[32 + lane]) : 0.f);
                    qm[k] = dot4(m0[k], sw[lane]) + ((lane < 18) ? dot4(m1[k], sw[32 + lane]) : 0.f);
                }
                #pragma unroll
                for (int off = 16; off; off >>= 1) {
                    #pragma unroll
                    for (int k = 0; k < 4; k++) {
                        q3[k] += __shfl_xor_sync(0xffffffffu, q3[k], off);
                        qm[k] += __shfl_xor_sync(0xffffffffu, qm[k], off);
                    }
                }
                float ee[4];
                #pragma unroll
                for (int k = 0; k < 4; k++) {
                    float sa = p1 + __shfl_sync(0xffffffffu, pd2, j + k) + q3[k];
                    float sm = pm1 + __shfl_sync(0xffffffffu, pmd2, j + k) + qm[k] + bias;
                    float lrv = (sa > 0.f) ? sa : ALPHA * sa;
                    ee[k] = __expf(-lrv * tanh_fast(sm) * (1.0f / (float)E_TOT));
                }
                #pragma unroll
                for (int k = 0; k < 4; k++) {
                    rs += ee[k];
                    a0.x += ee[k] * m0[k].x; a0.y += ee[k] * m0[k].y;
                    a0.z += ee[k] * m0[k].z; a0.w += ee[k] * m0[k].w;
                }
                if (lane < 18) {
                    #pragma unroll
                    for (int k = 0; k < 4; k++) {
                        a1.x += ee[k] * m1[k].x; a1.y += ee[k] * m1[k].y;
                        a1.z += ee[k] * m1[k].z; a1.w += ee[k] * m1[k].w;
                    }
                }
                if (lane == 0) {
                    #pragma unroll
                    for (int k = 0; k < 4; k++) eslot[j + k] = ee[k];
                }
            }
            for (; j < cnt; j++) {
                int eid = __shfl_sync(0xffffffffu, rec.y, j);
                const float4* p0 = (eid < E1C)
                    ? (const float4*)emb1 + (size_t)eid * 50
                    : (const float4*)emb2 + (size_t)(eid - E1C) * 50;
                float4 m0 = p0[lane];
                float4 m1 = (lane < 18) ? p0[32 + lane] : make_float4(0, 0, 0, 0);
                float q3 = dot4(m0, sv[lane]) + ((lane < 18) ? dot4(m1, sv[32 + lane]) : 0.f);
                float qm = dot4(m0, sw[lane]) + ((lane < 18) ? dot4(m1, sw[32 + lane]) : 0.f);
                #pragma unroll
                for (int off = 16; off; off >>= 1) {
                    q3 += __shfl_xor_sync(0xffffffffu, q3, off);
                    qm += __shfl_xor_sync(0xffffffffu, qm, off);
                }
                float sa = p1 + __shfl_sync(0xffffffffu, pd2, j) + q3;
                float sm = pm1 + __shfl_sync(0xffffffffu, pmd2, j) + qm + bias;
                float lrv = (sa > 0.f) ? sa : ALPHA * sa;
                float e0 = __expf(-lrv * tanh_fast(sm) * (1.0f / (float)E_TOT));
                rs += e0;
                a0.x += e0 * m0.x; a0.y += e0 * m0.y; a0.z += e0 * m0.z; a0.w += e0 * m0.w;
                if (lane < 18) {
                    a1.x += e0 * m1.x; a1.y += e0 * m1.y; a1.z += e0 * m1.z; a1.w += e0 * m1.w;
                }
                if (lane == 0) eslot[j] = e0;
            }
            asm volatile("bar.sync %0, 64;" :: "r"(barid) : "memory");
        }

        // write G packed bf16 + rowsum
        unsigned h0, l0, h1, l1;
        split_pack2(a0.x, a0.y, h0, l0);
        split_pack2(a0.z, a0.w, h1, l1);
        size_t o = (size_t)node * 100 + 2 * lane;
        *(uint2*)&g_gqh[o] = make_uint2(h0, h1);
        *(uint2*)&g_gql[o] = make_uint2(l0, l1);
        if (lane < 18) {
            split_pack2(a1.x, a1.y, h0, l0);
            split_pack2(a1.z, a1.w, h1, l1);
            size_t o2 = (size_t)node * 100 + 64 + 2 * lane;
            *(uint2*)&g_gqh[o2] = make_uint2(h0, h1);
            *(uint2*)&g_gql[o2] = make_uint2(l0, l1);
        }
        if (lane == 0) g_rs[node] = rs;
    } else {
        for (int b = 0; b < nb; b++) {
            int base = beg + (b << 5);
            int cnt  = min(32, end - base);
            int2 rec = (lane < cnt) ? g_rec[base + lane] : make_int2(0, 0);
            const float* eslot = s_ee[pair][b & 1];
            asm volatile("bar.sync %0, 64;" :: "r"(barid) : "memory");

            int j = 0;
            for (; j + 4 <= cnt; j += 4) {
                const float4* p[4];
                float e[4];
                #pragma unroll
                for (int k = 0; k < 4; k++) {
                    int dst = __shfl_sync(0xffffffffu, rec.x, j + k);
                    p[k] = (const float4*)g_X2 + (size_t)dst * 50;
                    e[k] = eslot[j + k];
                }
                float4 v[4], u[4];
                #pragma unroll
                for (int k = 0; k < 4; k++) v[k] = p[k][lane];
                if (lane < 18) {
                    #pragma unroll
                    for (int k = 0; k < 4; k++) u[k] = p[k][32 + lane];
                }
                #pragma unroll
                for (int k = 0; k < 4; k++) {
                    a0.x += e[k] * v[k].x; a0.y += e[k] * v[k].y;
                    a0.z += e[k] * v[k].z; a0.w += e[k] * v[k].w;
                }
                if (lane < 18) {
                    #pragma unroll
                    for (int k = 0; k < 4; k++) {
                        a1.x += e[k] * u[k].x; a1.y += e[k] * u[k].y;
                        a1.z += e[k] * u[k].z; a1.w += e[k] * u[k].w;
                    }
                }
            }
            for (; j < cnt; j++) {
                int dst = __shfl_sync(0xffffffffu, rec.x, j);
                const float4* p0 = (const float4*)g_X2 + (size_t)dst * 50;
                float e0 = eslot[j];
                float4 v0 = p0[lane];
                a0.x += e0 * v0.x; a0.y += e0 * v0.y; a0.z += e0 * v0.z; a0.w += e0 * v0.w;
                if (lane < 18) {
                    float4 u0 = p0[32 + lane];
                    a1.x += e0 * u0.x; a1.y += e0 * u0.y; a1.z += e0 * u0.z; a1.w += e0 * u0.w;
                }
            }
        }
        float4* Out = (float4*)g_ACC + (size_t)node * 50;
        Out[lane] = a0;
        if (lane < 18) Out[32 + lane] = a1;
    }
}

// ---- streams/events created once at load time ----
struct GraphResources {
    cudaStream_t s1, s2;
    cudaEvent_t evStart, evT, evX2, evX1, evCSR;
    GraphResources() {
        cudaStreamCreateWithFlags(&s1, cudaStreamNonBlocking);
        cudaStreamCreateWithFlags(&s2, cudaStreamNonBlocking);
        cudaEventCreateWithFlags(&evStart, cudaEventDisableTiming);
        cudaEventCreateWithFlags(&evT, cudaEventDisableTiming);
        cudaEventCreateWithFlags(&evX2, cudaEventDisableTiming);
        cudaEventCreateWithFlags(&evX1, cudaEventDisableTiming);
        cudaEventCreateWithFlags(&evCSR, cudaEventDisableTiming);
    }
};
static GraphResources g_gr;

extern "C" void kernel_launch(void* const* d_in, const int* in_sizes, int n_in,
                              void* d_out, int out_size) {
    const float* x    = (const float*)d_in[0];
    const int*   edge = (const int*)  d_in[1];
    const float* ee1  = (const float*)d_in[2];
    const int*   edg2 = (const int*)  d_in[3];
    const float* ee2  = (const float*)d_in[4];
    const float* a    = (const float*)d_in[5];
    const float* a2   = (const float*)d_in[6];
    const float* mw   = (const float*)d_in[7];
    const float* mb   = (const float*)d_in[8];
    float* out = (float*)d_out;

    cudaFuncSetAttribute(tgemm_kernel, cudaFuncAttributeMaxDynamicSharedMemorySize, SMEM_BYTES);

    int ggrid = (N_NODES + BM - 1) / BM;
    cudaStream_t s0 = 0;

    unsigned *xqh_p, *xql_p, *gqh_p, *gql_p;
    cudaGetSymbolAddress((void**)&xqh_p, g_xqh);
    cudaGetSymbolAddress((void**)&xql_p, g_xql);
    cudaGetSymbolAddress((void**)&gqh_p, g_gqh);
    cudaGetSymbolAddress((void**)&gql_p, g_gql);

    cudaEventRecord(g_gr.evStart, s0);

    // s0 prep
    transpose_kernel<<<(300 * FDIM + 255) / 256, 256, 0, s0>>>(a);
    vw_kernel<<<1, 640, 0, s0>>>(a, a2, mw);
    pvec_kernel<<<N_NODES / 8, 256, 0, s0>>>(x);
    cudaEventRecord(g_gr.evT, s0);

    // s1: CSR build (deg -> scan (self-zeroing) -> fill)
    cudaStreamWaitEvent(g_gr.s1, g_gr.evStart, 0);
    deg_kernel<<<(E_TOT + 255) / 256, 256, 0, g_gr.s1>>>(edge, edg2);
    scan_kernel<<<1, 1024, 0, g_gr.s1>>>();
    fill_kernel<<<(E_TOT + 255) / 256, 256, 0, g_gr.s1>>>(edge, edg2);
    cudaEventRecord(g_gr.evCSR, g_gr.s1);

    // s2: pack_x, then the two precompute GEMMs
    cudaStreamWaitEvent(g_gr.s2, g_gr.evStart, 0);
    pack_x_kernel<<<(N_NODES * 50 + 255) / 256, 256, 0, g_gr.s2>>>(x);
    cudaStreamWaitEvent(g_gr.s2, g_gr.evT, 0);
    tgemm_kernel<<<ggrid, TG_THREADS, SMEM_BYTES, g_gr.s2>>>(xqh_p, xql_p, N_NODES, 100, 1, nullptr);  // X2
    cudaEventRecord(g_gr.evX2, g_gr.s2);
    tgemm_kernel<<<ggrid, TG_THREADS, SMEM_BYTES, g_gr.s2>>>(xqh_p, xql_p, N_NODES, 0, 0, nullptr);    // X1
    cudaEventRecord(g_gr.evX1, g_gr.s2);

    // s0: fused score+gather (needs pvec on s0, CSR, X2)
    cudaStreamWaitEvent(s0, g_gr.evCSR, 0);
    cudaStreamWaitEvent(s0, g_gr.evX2, 0);
    gather_fused<<<(N_NODES + 3) / 4, 256, 0, s0>>>(ee1, ee2, mb);

    cudaStreamWaitEvent(s0, g_gr.evX1, 0);
    tgemm_kernel<<<ggrid, TG_THREADS, SMEM_BYTES, s0>>>(gqh_p, gql_p, N_NODES, 200, 2, out);  // final
}

// round 14
// speedup vs baseline: 1.1476x; 1.1476x over previous
#include <cuda_runtime.h>
#include <cuda_bf16.h>
#include <math.h>
#include <stdint.h>

#define N_NODES 50000
#define FDIM    200
#define E1C     400000
#define E2C     100000
#define E_TOT   500000
#define ALPHA   0.2f

// tensor-GEMM tiling (bf16 3x split, K pairs), 512 threads / 16 warps
#define BM 128
#define KP_TILE 20
#define NKB 5
#define A_STRIDE 20
#define B_STRIDE 200
#define A_BUFU (BM * A_STRIDE)
#define B_BUFU (KP_TILE * B_STRIDE + 64)
#define SMEM_UINTS (4 * A_BUFU + 4 * B_BUFU)
#define SMEM_BYTES (SMEM_UINTS * 4)
#define TG_THREADS 512

// ---- device scratch ----
__device__ float g_X1[(size_t)N_NODES * FDIM];
__device__ float g_X2[(size_t)N_NODES * FDIM];
__device__ float g_ACC[(size_t)N_NODES * FDIM];
__device__ float g_rs[N_NODES];
__device__ float g_p[4 * N_NODES];
__device__ float g_v[600];
__device__ float g_w[600];
__device__ unsigned g_bqh[300 * FDIM];
__device__ unsigned g_bql[300 * FDIM];
__device__ unsigned g_xqh[(size_t)N_NODES * 100];
__device__ unsigned g_xql[(size_t)N_NODES * 100];
__device__ unsigned g_gqh[(size_t)N_NODES * 100];
__device__ unsigned g_gql[(size_t)N_NODES * 100];
__device__ float g_ee[E_TOT];
__device__ int  g_deg[N_NODES];          // zero-init at load; scan re-zeroes each run
__device__ int  g_off[N_NODES + 1];
__device__ int  g_cur[N_NODES];
__device__ int2 g_rec[E_TOT];
__device__ int4 g_rec3[E_TOT];

__device__ __forceinline__ float dot4(float4 a, float4 b) {
    return a.x * b.x + a.y * b.y + a.z * b.z + a.w * b.w;
}

__device__ __forceinline__ float tanh_fast(float x) {
    float y;
    asm("tanh.approx.f32 %0, %1;" : "=f"(y) : "f"(x));
    return y;
}

__device__ __forceinline__ void split_pack2(float f0, float f1,
                                            unsigned& hi, unsigned& lo) {
    __nv_bfloat162 h = __float22bfloat162_rn(make_float2(f0, f1));
    hi = *reinterpret_cast<unsigned*>(&h);
    float l0 = f0 - __bfloat162float(h.x);
    float l1 = f1 - __bfloat162float(h.y);
    __nv_bfloat162 l = __float22bfloat162_rn(make_float2(l0, l1));
    lo = *reinterpret_cast<unsigned*>(&l);
}

__device__ __forceinline__ void mma_bf16_k16(float* c, const unsigned* a,
                                             unsigned b0, unsigned b1) {
    asm volatile("mma.sync.aligned.m16n8k16.row.col.f32.bf16.bf16.f32 "
                 "{%0,%1,%2,%3}, {%4,%5,%6,%7}, {%8,%9}, {%0,%1,%2,%3};"
                 : "+f"(c[0]), "+f"(c[1]), "+f"(c[2]), "+f"(c[3])
                 : "r"(a[0]), "r"(a[1]), "r"(a[2]), "r"(a[3]), "r"(b0), "r"(b1));
}

__device__ __forceinline__ void mma_bf16_k8(float* c, unsigned a0, unsigned a1,
                                            unsigned b0) {
    asm volatile("mma.sync.aligned.m16n8k8.row.col.f32.bf16.bf16.f32 "
                 "{%0,%1,%2,%3}, {%4,%5}, {%6}, {%0,%1,%2,%3};"
                 : "+f"(c[0]), "+f"(c[1]), "+f"(c[2]), "+f"(c[3])
                 : "r"(a0), "r"(a1), "r"(b0));
}

__device__ __forceinline__ void cp_async16(void* smem_dst, const void* gmem_src, bool pred) {
    uint32_t s = (uint32_t)__cvta_generic_to_shared(smem_dst);
    int sz = pred ? 16 : 0;
    asm volatile("cp.async.cg.shared.global [%0], [%1], 16, %2;"
                 :: "r"(s), "l"(gmem_src), "r"(sz));
}
__device__ __forceinline__ void cp_commit() {
    asm volatile("cp.async.commit_group;");
}
template<int N>
__device__ __forceinline__ void cp_wait() {
    asm volatile("cp.async.wait_group %0;" :: "n"(N));
}

// ---------------- CSR build ----------------
__global__ __launch_bounds__(256) void deg_kernel(const int* __restrict__ edge,
                                                  const int* __restrict__ edge2) {
    int e = blockIdx.x * blockDim.x + threadIdx.x;
    if (e >= E_TOT) return;
    int src = (e < E1C) ? edge[e] : edge2[e - E1C];
    atomicAdd(&g_deg[src], 1);
}

__global__ __launch_bounds__(1024) void scan_kernel() {
    __shared__ int warp_sums[32];
    __shared__ int s_total;
    __shared__ int s_run;
    int t = threadIdx.x;
    int lane = t & 31, wid = t >> 5;
    if (t == 0) s_run = 0;
    __syncthreads();
    for (int base = 0; base < N_NODES; base += 1024) {
        int idx = base + t;
        int v = 0;
        if (idx < N_NODES) {
            v = g_deg[idx];
            g_deg[idx] = 0;
        }
        int incl = v;
        #pragma unroll
        for (int d = 1; d < 32; d <<= 1) {
            int n = __shfl_up_sync(0xffffffffu, incl, d);
            if (lane >= d) incl += n;
        }
        if (lane == 31) warp_sums[wid] = incl;
        __syncthreads();
        if (wid == 0) {
            int ws = warp_sums[lane];
            int wincl = ws;
            #pragma unroll
            for (int d = 1; d < 32; d <<= 1) {
                int n = __shfl_up_sync(0xffffffffu, wincl, d);
                if (lane >= d) wincl += n;
            }
            warp_sums[lane] = wincl - ws;
            if (lane == 31) s_total = wincl;
        }
        __syncthreads();
        int excl = s_run + warp_sums[wid] + incl - v;
        if (idx < N_NODES) { g_off[idx] = excl; g_cur[idx] = excl; }
        __syncthreads();
        if (t == 0) s_run += s_total;
        __syncthreads();
    }
    if (t == 0) g_off[N_NODES] = s_run;
}

__global__ __launch_bounds__(256) void fill_kernel(const int* __restrict__ edge,
                                                   const int* __restrict__ edge2) {
    int e = blockIdx.x * blockDim.x + threadIdx.x;
    if (e >= E_TOT) return;
    int src, dst;
    if (e < E1C) { src = edge[e]; dst = edge[E1C + e]; }
    else         { src = edge2[e - E1C]; dst = edge2[E2C + (e - E1C)]; }
    int pos = atomicAdd(&g_cur[src], 1);
    g_rec[pos] = make_int2(dst, e);
}

__global__ __launch_bounds__(256) void pack_kernel() {
    int i = blockIdx.x * blockDim.x + threadIdx.x;
    if (i >= E_TOT) return;
    int2 r = g_rec[i];
    float e = g_ee[r.y];
    g_rec3[i] = make_int4(r.x, r.y, __float_as_int(e), 0);
}

// ---------------- weights prep ----------------
__global__ __launch_bounds__(256) void transpose_kernel(const float* __restrict__ a) {
    int i = blockIdx.x * blockDim.x + threadIdx.x;
    if (i >= 300 * FDIM) return;
    int jp = i / FDIM;
    int n  = i % FDIM;
    float f0 = a[n * 600 + 2 * jp];
    float f1 = a[n * 600 + 2 * jp + 1];
    unsigned hi, lo;
    split_pack2(f0, f1, hi, lo);
    g_bqh[i] = hi;
    g_bql[i] = lo;
}

__global__ __launch_bounds__(256) void pack_x_kernel(const float* __restrict__ x) {
    int i = blockIdx.x * blockDim.x + threadIdx.x;
    if (i >= N_NODES * 50) return;
    int m = i / 50, c = i % 50;
    float4 v = ((const float4*)x)[i];
    unsigned h0, l0, h1, l1;
    split_pack2(v.x, v.y, h0, l0);
    split_pack2(v.z, v.w, h1, l1);
    size_t o = (size_t)m * 100 + 2 * c;
    *(uint2*)&g_xqh[o] = make_uint2(h0, h1);
    *(uint2*)&g_xql[o] = make_uint2(l0, l1);
}

__global__ __launch_bounds__(640) void vw_kernel(const float* __restrict__ a,
                                                 const float* __restrict__ a2,
                                                 const float* __restrict__ mw) {
    int j = threadIdx.x;
    if (j >= 600) return;
    float v = 0.f, w = 0.f;
    for (int o = 0; o < FDIM; o++) {
        float aj = a[o * 600 + j];
        v += aj * a2[o];
        w += aj * mw[o];
    }
    g_v[j] = v;
    g_w[j] = w;
}

__global__ __launch_bounds__(256) void pvec_kernel(const float* __restrict__ x) {
    __shared__ float4 sv[100];
    __shared__ float4 sw[100];
    int t = threadIdx.x;
    if (t < 100)       sv[t]       = ((const float4*)g_v)[t];
    else if (t < 200)  sw[t - 100] = ((const float4*)g_w)[t - 100];
    __syncthreads();

    int warp = t >> 5, lane = t & 31;
    int node = blockIdx.x * 8 + warp;
    if (node >= N_NODES) return;

    const float4* xr = (const float4*)x + (size_t)node * 50;
    float4 x0 = xr[lane];
    float4 x1 = (lane < 18) ? xr[32 + lane] : make_float4(0, 0, 0, 0);

    float p1  = dot4(x0, sv[lane])      + ((lane < 18) ? dot4(x1, sv[32 + lane]) : 0.f);
    float p2  = dot4(x0, sv[50 + lane]) + ((lane < 18) ? dot4(x1, sv[82 + lane]) : 0.f);
    float pm1 = dot4(x0, sw[lane])      + ((lane < 18) ? dot4(x1, sw[32 + lane]) : 0.f);
    float pm2 = dot4(x0, sw[50 + lane]) + ((lane < 18) ? dot4(x1, sw[82 + lane]) : 0.f);

    #pragma unroll
    for (int off = 16; off; off >>= 1) {
        p1  += __shfl_xor_sync(0xffffffffu, p1, off);
        p2  += __shfl_xor_sync(0xffffffffu, p2, off);
        pm1 += __shfl_xor_sync(0xffffffffu, pm1, off);
        pm2 += __shfl_xor_sync(0xffffffffu, pm2, off);
    }
    if (lane == 0) {
        g_p[node]               = p1;
        g_p[N_NODES + node]     = p2;
        g_p[2 * N_NODES + node] = pm1;
        g_p[3 * N_NODES + node] = pm2;
    }
}

// ---------------- phase 1: streaming edge scores (2 edges per warp) ----------------
__global__ __launch_bounds__(256) void score_kernel(const int* __restrict__ edge,
                                                    const float* __restrict__ emb1,
                                                    const int* __restrict__ edge2,
                                                    const float* __restrict__ emb2,
                                                    const float* __restrict__ mlp_b) {
    __shared__ float4 sv[50];
    __shared__ float4 sw[50];
    int t = threadIdx.x;
    if (t < 50)       sv[t]      = *(const float4*)&g_v[400 + t * 4];
    else if (t < 100) sw[t - 50] = *(const float4*)&g_w[400 + (t - 50) * 4];
    __syncthreads();

    int warp = t >> 5, lane = t & 31;
    int e0 = blockIdx.x * 16 + warp * 2;    // two consecutive edges per warp

    int srcA, dstA, srcB, dstB;
    const float4 *embA, *embB;
    bool hasB = (e0 + 1) < E_TOT;
    if (e0 >= E_TOT) return;

    if (e0 < E1C) {
        srcA = edge[e0]; dstA = edge[E1C + e0];
        embA = (const float4*)emb1 + (size_t)e0 * 50;
    } else {
        int r = e0 - E1C;
        srcA = edge2[r]; dstA = edge2[E2C + r];
        embA = (const float4*)emb2 + (size_t)r * 50;
    }
    int e1 = e0 + 1;
    if (hasB) {
        if (e1 < E1C) {
            srcB = edge[e1]; dstB = edge[E1C + e1];
            embB = (const float4*)emb1 + (size_t)e1 * 50;
        } else {
            int r = e1 - E1C;
            srcB = edge2[r]; dstB = edge2[E2C + r];
            embB = (const float4*)emb2 + (size_t)r * 50;
        }
    } else { srcB = srcA; dstB = dstA; embB = embA; }

    float4 svl = __ldg((const float4*)&sv[lane]);  // keep smem read simple
    svl = sv[lane];
    float4 swl = sw[lane];
    float4 a0 = embA[lane];
    float4 b0 = embB[lane];
    float4 a1 = (lane < 18) ? embA[32 + lane] : make_float4(0, 0, 0, 0);
    float4 b1 = (lane < 18) ? embB[32 + lane] : make_float4(0, 0, 0, 0);

    float q3A = dot4(a0, svl) + ((lane < 18) ? dot4(a1, sv[32 + lane]) : 0.f);
    float qmA = dot4(a0, swl) + ((lane < 18) ? dot4(a1, sw[32 + lane]) : 0.f);
    float q3B = dot4(b0, svl) + ((lane < 18) ? dot4(b1, sv[32 + lane]) : 0.f);
    float qmB = dot4(b0, swl) + ((lane < 18) ? dot4(b1, sw[32 + lane]) : 0.f);

    #pragma unroll
    for (int off = 16; off; off >>= 1) {
        q3A += __shfl_xor_sync(0xffffffffu, q3A, off);
        qmA += __shfl_xor_sync(0xffffffffu, qmA, off);
        q3B += __shfl_xor_sync(0xffffffffu, q3B, off);
        qmB += __shfl_xor_sync(0xffffffffu, qmB, off);
    }

    if (lane == 0) {
        float bias = mlp_b[0];
        float saA = g_p[srcA] + g_p[N_NODES + dstA] + q3A;
        float smA = g_p[2 * N_NODES + srcA] + g_p[3 * N_NODES + dstA] + qmA + bias;
        float lrA = (saA > 0.f) ? saA : ALPHA * saA;
        g_ee[e0] = __expf(-lrA * tanh_fast(smA) * (1.0f / (float)E_TOT));
        if (hasB) {
            float saB = g_p[srcB] + g_p[N_NODES + dstB] + q3B;
            float smB = g_p[2 * N_NODES + srcB] + g_p[3 * N_NODES + dstB] + qmB + bias;
            float lrB = (saB > 0.f) ? saB : ALPHA * saB;
            g_ee[e1] = __expf(-lrB * tanh_fast(smB) * (1.0f / (float)E_TOT));
        }
    }
}

// ---------------- bf16 3x tensor-core GEMM (512 threads, 4mg x 4ng) ----------------
__device__ __forceinline__ void stage_tile(unsigned* Ah, unsigned* Al,
                                           unsigned* Bh, unsigned* Bl,
                                           const unsigned* gAh, const unsigned* gAl,
                                           int M, int row0, int jp0, int kb, int t) {
    int kp0 = kb * KP_TILE;
    #pragma unroll
    for (int i = 0; i < 2; i++) {
        int idx = t + i * TG_THREADS;
        if (idx < 640) {
            int r = idx / 5, c4 = idx % 5;
            bool ok = (row0 + r) < M;
            size_t go = (size_t)(row0 + r) * 100 + kp0 + c4 * 4;
            cp_async16(Ah + r * A_STRIDE + c4 * 4, gAh + go, ok);
            cp_async16(Al + r * A_STRIDE + c4 * 4, gAl + go, ok);
        }
    }
    const unsigned* sH = g_bqh + (size_t)(jp0 + kp0) * FDIM;
    const unsigned* sL = g_bql + (size_t)(jp0 + kp0) * FDIM;
    #pragma unroll
    for (int i = 0; i < 2; i++) {
        int idx = t + i * TG_THREADS;
        if (idx < 1000) {
            int row = idx / 50, c4 = idx % 50;
            cp_async16(Bh + row * B_STRIDE + c4 * 4, sH + idx * 4, true);
            cp_async16(Bl + row * B_STRIDE + c4 * 4, sL + idx * 4, true);
        }
    }
}

// dest 0 -> g_X1, 1 -> g_X2, 2 -> final epilogue into fout
__global__ void __launch_bounds__(TG_THREADS, 1)
tgemm_kernel(const unsigned* __restrict__ gAh, const unsigned* __restrict__ gAl,
             int M, int jp0, int dest, float* __restrict__ fout) {
    extern __shared__ unsigned smu_[];
    unsigned* Ah[2] = { smu_, smu_ + A_BUFU };
    unsigned* Al[2] = { smu_ + 2 * A_BUFU, smu_ + 3 * A_BUFU };
    unsigned* Bh[2] = { smu_ + 4 * A_BUFU, smu_ + 4 * A_BUFU + B_BUFU };
    unsigned* Bl[2] = { smu_ + 4 * A_BUFU + 2 * B_BUFU, smu_ + 4 * A_BUFU + 3 * B_BUFU };

    int row0 = blockIdx.x * BM;
    int t = threadIdx.x;
    int warp = t >> 5, lane = t & 31;
    int mg = warp >> 2;
    int ng = warp & 3;
    int n0 = ng * 56;
    int m0w = mg * 32;
    int lr = lane >> 2;
    int lc = lane & 3;

    float acc[2][7][4];
    #pragma unroll
    for (int a_ = 0; a_ < 2; a_++)
        #pragma unroll
        for (int b_ = 0; b_ < 7; b_++)
            #pragma unroll
            for (int c_ = 0; c_ < 4; c_++) acc[a_][b_][c_] = 0.f;

    stage_tile(Ah[0], Al[0], Bh[0], Bl[0], gAh, gAl, M, row0, jp0, 0, t);
    cp_commit();

    for (int kb = 0; kb < NKB; kb++) {
        int cur = kb & 1;
        if (kb + 1 < NKB) {
            stage_tile(Ah[cur ^ 1], Al[cur ^ 1], Bh[cur ^ 1], Bl[cur ^ 1],
                       gAh, gAl, M, row0, jp0, kb + 1, t);
            cp_commit();
            cp_wait<1>();
        } else {
            cp_wait<0>();
        }
        __syncthreads();

        const unsigned* Ach = Ah[cur];
        const unsigned* Acl = Al[cur];
        const unsigned* Bch = Bh[cur];
        const unsigned* Bcl = Bl[cur];

        #pragma unroll
        for (int st = 0; st < 2; st++) {
            int kpb = st * 8;
            unsigned ah[2][4], al[2][4];
            #pragma unroll
            for (int mt = 0; mt < 2; mt++) {
                int mrow = m0w + mt * 16 + lr;
                ah[mt][0] = Ach[mrow * A_STRIDE + kpb + lc];
                ah[mt][1] = Ach[(mrow + 8) * A_STRIDE + kpb + lc];
                ah[mt][2] = Ach[mrow * A_STRIDE + kpb + lc + 4];
                ah[mt][3] = Ach[(mrow + 8) * A_STRIDE + kpb + lc + 4];
                al[mt][0] = Acl[mrow * A_STRIDE + kpb + lc];
                al[mt][1] = Acl[(mrow + 8) * A_STRIDE + kpb + lc];
                al[mt][2] = Acl[mrow * A_STRIDE + kpb + lc + 4];
                al[mt][3] = Acl[(mrow + 8) * A_STRIDE + kpb + lc + 4];
            }
            #pragma unroll
            for (int nt = 0; nt < 7; nt++) {
                int nc = n0 + nt * 8 + lr;
                unsigned bh0 = Bch[(kpb + lc) * B_STRIDE + nc];
                unsigned bh1 = Bch[(kpb + lc + 4) * B_STRIDE + nc];
                unsigned bl0 = Bcl[(kpb + lc) * B_STRIDE + nc];
                unsigned bl1 = Bcl[(kpb + lc + 4) * B_STRIDE + nc];
                #pragma unroll
                for (int mt = 0; mt < 2; mt++) {
                    mma_bf16_k16(acc[mt][nt], ah[mt], bh0, bh1);
                    mma_bf16_k16(acc[mt][nt], ah[mt], bl0, bl1);
                    mma_bf16_k16(acc[mt][nt], al[mt], bh0, bh1);
                }
            }
        }
        {
            unsigned ah8[2][2], al8[2][2];
            #pragma unroll
            for (int mt = 0; mt < 2; mt++) {
                int mrow = m0w + mt * 16 + lr;
                ah8[mt][0] = Ach[mrow * A_STRIDE + 16 + lc];
                ah8[mt][1] = Ach[(mrow + 8) * A_STRIDE + 16 + lc];
                al8[mt][0] = Acl[mrow * A_STRIDE + 16 + lc];
                al8[mt][1] = Acl[(mrow + 8) * A_STRIDE + 16 + lc];
            }
            #pragma unroll
            for (int nt = 0; nt < 7; nt++) {
                int nc = n0 + nt * 8 + lr;
                unsigned bh0 = Bch[(16 + lc) * B_STRIDE + nc];
                unsigned bl0 = Bcl[(16 + lc) * B_STRIDE + nc];
                #pragma unroll
                for (int mt = 0; mt < 2; mt++) {
                    mma_bf16_k8(acc[mt][nt], ah8[mt][0], ah8[mt][1], bh0);
                    mma_bf16_k8(acc[mt][nt], ah8[mt][0], ah8[mt][1], bl0);
                    mma_bf16_k8(acc[mt][nt], al8[mt][0], al8[mt][1], bh0);
                }
            }
        }
        __syncthreads();
    }

    if (dest != 2) {
        float* Out = (dest == 0) ? g_X1 : g_X2;
        #pragma unroll
        for (int mt = 0; mt < 2; mt++) {
            int r0 = row0 + m0w + mt * 16 + lr;
            #pragma unroll
            for (int nt = 0; nt < 7; nt++) {
                int col = n0 + nt * 8 + 2 * lc;
                if (col >= FDIM) continue;
                if (r0 < M)
                    *(float2*)(Out + (size_t)r0 * FDIM + col) =
                        make_float2(acc[mt][nt][0], acc[mt][nt][1]);
                if (r0 + 8 < M)
                    *(float2*)(Out + (size_t)(r0 + 8) * FDIM + col) =
                        make_float2(acc[mt][nt][2], acc[mt][nt][3]);
            }
        }
    } else {
        #pragma unroll
        for (int mt = 0; mt < 2; mt++) {
            #pragma unroll
            for (int h = 0; h < 2; h++) {
                int r = row0 + m0w + mt * 16 + lr + 8 * h;
                if (r >= M) continue;
                float rs = g_rs[r];
                if (rs == 0.f) {
                    #pragma unroll
                    for (int nt = 0; nt < 7; nt++) {
                        int col = n0 + nt * 8 + 2 * lc;
                        if (col >= FDIM) continue;
                        *(float2*)(fout + (size_t)r * FDIM + col) = make_float2(0.f, 0.f);
                    }
                } else {
                    float inv = 1.f / rs;
                    #pragma unroll
                    for (int nt = 0; nt < 7; nt++) {
                        int col = n0 + nt * 8 + 2 * lc;
                        if (col >= FDIM) continue;
                        size_t idx = (size_t)r * FDIM + col;
                        float2 x1 = *(const float2*)(g_X1 + idx);
                        float2 av = *(const float2*)(g_ACC + idx);
                        float g0 = acc[mt][nt][2 * h + 0];
                        float g1 = acc[mt][nt][2 * h + 1];
                        float v0 = x1.x + (av.x + g0) * inv;
                        float v1 = x1.y + (av.y + g1) * inv;
                        v0 = (v0 > 0.f) ? v0 : (expf(v0) - 1.f);
                        v1 = (v1 > 0.f) ? v1 : (expf(v1) - 1.f);
                        *(float2*)(fout + idx) = make_float2(v0, v1);
                    }
                }
            }
        }
    }
}

// ---------------- phase 2: role-split gather (G written packed bf16) ----------------
__global__ __launch_bounds__(256) void gather_kernel(const float* __restrict__ emb1,
                                                     const float* __restrict__ emb2) {
    int t = threadIdx.x;
    int warp = t >> 5, lane = t & 31;
    int node = blockIdx.x * 4 + (warp >> 1);
    int role = warp & 1;
    if (node >= N_NODES) return;

    int beg = g_off[node];
    int end = g_off[node + 1];

    float4 a0 = make_float4(0, 0, 0, 0), a1 = a0;
    float rs = 0.f;

    for (int base = beg; base < end; base += 32) {
        int cnt = min(32, end - base);
        int4 rr = (lane < cnt) ? g_rec3[base + lane] : make_int4(0, 0, 0, 0);

        int j = 0;
        for (; j + 4 <= cnt; j += 4) {
            const float4* p[4];
            float e[4];
            #pragma unroll
            for (int k = 0; k < 4; k++) {
                int dstk = __shfl_sync(0xffffffffu, rr.x, j + k);
                int eidk = __shfl_sync(0xffffffffu, rr.y, j + k);
                e[k] = __int_as_float(__shfl_sync(0xffffffffu, rr.z, j + k));
                if (role == 0) {
                    p[k] = (eidk < E1C) ? (const float4*)emb1 + (size_t)eidk * 50
                                        : (const float4*)emb2 + (size_t)(eidk - E1C) * 50;
                } else {
                    p[k] = (const float4*)g_X2 + (size_t)dstk * 50;
                }
            }
            float4 v[4], u[4];
            #pragma unroll
            for (int k = 0; k < 4; k++) v[k] = p[k][lane];
            if (lane < 18) {
                #pragma unroll
                for (int k = 0; k < 4; k++) u[k] = p[k][32 + lane];
            }
            #pragma unroll
            for (int k = 0; k < 4; k++) {
                rs += e[k];
                a0.x += e[k] * v[k].x; a0.y += e[k] * v[k].y;
                a0.z += e[k] * v[k].z; a0.w += e[k] * v[k].w;
            }
            if (lane < 18) {
                #pragma unroll
                for (int k = 0; k < 4; k++) {
                    a1.x += e[k] * u[k].x; a1.y += e[k] * u[k].y;
                    a1.z += e[k] * u[k].z; a1.w += e[k] * u[k].w;
                }
            }
        }
        for (; j < cnt; j++) {
            int dst0 = __shfl_sync(0xffffffffu, rr.x, j);
            int eid0 = __shfl_sync(0xffffffffu, rr.y, j);
            float e0 = __int_as_float(__shfl_sync(0xffffffffu, rr.z, j));
            const float4* p0;
            if (role == 0) {
                p0 = (eid0 < E1C) ? (const float4*)emb1 + (size_t)eid0 * 50
                                  : (const float4*)emb2 + (size_t)(eid0 - E1C) * 50;
            } else {
                p0 = (const float4*)g_X2 + (size_t)dst0 * 50;
            }
            float4 v0 = p0[lane];
            rs += e0;
            a0.x += e0 * v0.x; a0.y += e0 * v0.y; a0.z += e0 * v0.z; a0.w += e0 * v0.w;
            if (lane < 18) {
                float4 u0 = p0[32 + lane];
                a1.x += e0 * u0.x; a1.y += e0 * u0.y; a1.z += e0 * u0.z; a1.w += e0 * u0.w;
            }
        }
    }

    if (role == 0) {
        unsigned h0, l0, h1, l1;
        split_pack2(a0.x, a0.y, h0, l0);
        split_pack2(a0.z, a0.w, h1, l1);
        size_t o = (size_t)node * 100 + 2 * lane;
        *(uint2*)&g_gqh[o] = make_uint2(h0, h1);
        *(uint2*)&g_gql[o] = make_uint2(l0, l1);
        if (lane < 18) {
            split_pack2(a1.x, a1.y, h0, l0);
            split_pack2(a1.z, a1.w, h1, l1);
            size_t o2 = (size_t)node * 100 + 64 + 2 * lane;
            *(uint2*)&g_gqh[o2] = make_uint2(h0, h1);
            *(uint2*)&g_gql[o2] = make_uint2(l0, l1);
        }
        if (lane == 0) g_rs[node] = rs;
    } else {
        float4* Out = (float4*)g_ACC + (size_t)node * 50;
        Out[lane] = a0;
        if (lane < 18) Out[32 + lane] = a1;
    }
}

// ---- streams/events created once at load time ----
struct GraphResources {
    cudaStream_t s1, s2;
    cudaEvent_t evStart, evT, evX2, evX1, evCSR;
    GraphResources() {
        cudaStreamCreateWithFlags(&s1, cudaStreamNonBlocking);
        cudaStreamCreateWithFlags(&s2, cudaStreamNonBlocking);
        cudaEventCreateWithFlags(&evStart, cudaEventDisableTiming);
        cudaEventCreateWithFlags(&evT, cudaEventDisableTiming);
        cudaEventCreateWithFlags(&evX2, cudaEventDisableTiming);
        cudaEventCreateWithFlags(&evX1, cudaEventDisableTiming);
        cudaEventCreateWithFlags(&evCSR, cudaEventDisableTiming);
    }
};
static GraphResources g_gr;

extern "C" void kernel_launch(void* const* d_in, const int* in_sizes, int n_in,
                              void* d_out, int out_size) {
    const float* x    = (const float*)d_in[0];
    const int*   edge = (const int*)  d_in[1];
    const float* ee1  = (const float*)d_in[2];
    const int*   edg2 = (const int*)  d_in[3];
    const float* ee2  = (const float*)d_in[4];
    const float* a    = (const float*)d_in[5];
    const float* a2   = (const float*)d_in[6];
    const float* mw   = (const float*)d_in[7];
    const float* mb   = (const float*)d_in[8];
    float* out = (float*)d_out;

    cudaFuncSetAttribute(tgemm_kernel, cudaFuncAttributeMaxDynamicSharedMemorySize, SMEM_BYTES);

    int ggrid = (N_NODES + BM - 1) / BM;
    cudaStream_t s0 = 0;

    unsigned *xqh_p, *xql_p, *gqh_p, *gql_p;
    cudaGetSymbolAddress((void**)&xqh_p, g_xqh);
    cudaGetSymbolAddress((void**)&xql_p, g_xql);
    cudaGetSymbolAddress((void**)&gqh_p, g_gqh);
    cudaGetSymbolAddress((void**)&gql_p, g_gql);

    cudaEventRecord(g_gr.evStart, s0);

    // s0: prep (1-3), then score as 4th launch (profiled)
    transpose_kernel<<<(300 * FDIM + 255) / 256, 256, 0, s0>>>(a);
    vw_kernel<<<1, 640, 0, s0>>>(a, a2, mw);
    pvec_kernel<<<N_NODES / 8, 256, 0, s0>>>(x);
    cudaEventRecord(g_gr.evT, s0);
    score_kernel<<<(E_TOT + 15) / 16, 256, 0, s0>>>(edge, ee1, edg2, ee2, mb);

    // s2: pack_x + precompute GEMMs
    cudaStreamWaitEvent(g_gr.s2, g_gr.evStart, 0);
    pack_x_kernel<<<(N_NODES * 50 + 255) / 256, 256, 0, g_gr.s2>>>(x);
    cudaStreamWaitEvent(g_gr.s2, g_gr.evT, 0);
    tgemm_kernel<<<ggrid, TG_THREADS, SMEM_BYTES, g_gr.s2>>>(xqh_p, xql_p, N_NODES, 100, 1, nullptr);  // X2
    cudaEventRecord(g_gr.evX2, g_gr.s2);
    tgemm_kernel<<<ggrid, TG_THREADS, SMEM_BYTES, g_gr.s2>>>(xqh_p, xql_p, N_NODES, 0, 0, nullptr);    // X1
    cudaEventRecord(g_gr.evX1, g_gr.s2);

    // s1: CSR build
    cudaStreamWaitEvent(g_gr.s1, g_gr.evStart, 0);
    deg_kernel<<<(E_TOT + 255) / 256, 256, 0, g_gr.s1>>>(edge, edg2);
    scan_kernel<<<1, 1024, 0, g_gr.s1>>>();
    fill_kernel<<<(E_TOT + 255) / 256, 256, 0, g_gr.s1>>>(edge, edg2);
    cudaEventRecord(g_gr.evCSR, g_gr.s1);

    // pack recs (needs score + CSR), gather (needs pack + X2)
    cudaStreamWaitEvent(s0, g_gr.evCSR, 0);
    pack_kernel<<<(E_TOT + 255) / 256, 256, 0, s0>>>();
    cudaStreamWaitEvent(s0, g_gr.evX2, 0);
    gather_kernel<<<(N_NODES + 3) / 4, 256, 0, s0>>>(ee1, ee2);

    cudaStreamWaitEvent(s0, g_gr.evX1, 0);
    tgemm_kernel<<<ggrid, TG_THREADS, SMEM_BYTES, s0>>>(gqh_p, gql_p, N_NODES, 200, 2, out);  // final
}

// round 15
// speedup vs baseline: 1.2144x; 1.0582x over previous
#include <cuda_runtime.h>
#include <cuda_bf16.h>
#include <math.h>
#include <stdint.h>

#define N_NODES 50000
#define FDIM    200
#define E1C     400000
#define E2C     100000
#define E_TOT   500000
#define ALPHA   0.2f

// fused K=600 bf16 3x GEMM: 512 threads / 16 warps, 15 K-slabs of 20 pairs
#define BM 128
#define KP_TILE 20
#define NKB 15
#define KP_ROW 300            // pairs per A row: [x | ACCx/rs | G/rs]
#define A_STRIDE 20
#define B_STRIDE 200
#define A_BUFU (BM * A_STRIDE)
#define B_BUFU (KP_TILE * B_STRIDE + 64)
#define SMEM_UINTS (4 * A_BUFU + 4 * B_BUFU)
#define SMEM_BYTES (SMEM_UINTS * 4)
#define TG_THREADS 512

// ---- device scratch ----
__device__ float g_rs[N_NODES];
__device__ float g_p[4 * N_NODES];
__device__ float g_v[600];
__device__ float g_w[600];
__device__ unsigned g_bqh[300 * FDIM];
__device__ unsigned g_bql[300 * FDIM];
__device__ unsigned g_aqh[(size_t)N_NODES * KP_ROW];   // unified A operand hi
__device__ unsigned g_aql[(size_t)N_NODES * KP_ROW];   // unified A operand lo
__device__ float g_ee[E_TOT];
__device__ int  g_deg[N_NODES];          // zero-init at load; scan re-zeroes each run
__device__ int  g_off[N_NODES + 1];
__device__ int  g_cur[N_NODES];
__device__ int2 g_rec[E_TOT];
__device__ int4 g_rec3[E_TOT];

__device__ __forceinline__ float dot4(float4 a, float4 b) {
    return a.x * b.x + a.y * b.y + a.z * b.z + a.w * b.w;
}

__device__ __forceinline__ float tanh_fast(float x) {
    float y;
    asm("tanh.approx.f32 %0, %1;" : "=f"(y) : "f"(x));
    return y;
}

__device__ __forceinline__ void split_pack2(float f0, float f1,
                                            unsigned& hi, unsigned& lo) {
    __nv_bfloat162 h = __float22bfloat162_rn(make_float2(f0, f1));
    hi = *reinterpret_cast<unsigned*>(&h);
    float l0 = f0 - __bfloat162float(h.x);
    float l1 = f1 - __bfloat162float(h.y);
    __nv_bfloat162 l = __float22bfloat162_rn(make_float2(l0, l1));
    lo = *reinterpret_cast<unsigned*>(&l);
}

__device__ __forceinline__ void mma_bf16_k16(float* c, const unsigned* a,
                                             unsigned b0, unsigned b1) {
    asm volatile("mma.sync.aligned.m16n8k16.row.col.f32.bf16.bf16.f32 "
                 "{%0,%1,%2,%3}, {%4,%5,%6,%7}, {%8,%9}, {%0,%1,%2,%3};"
                 : "+f"(c[0]), "+f"(c[1]), "+f"(c[2]), "+f"(c[3])
                 : "r"(a[0]), "r"(a[1]), "r"(a[2]), "r"(a[3]), "r"(b0), "r"(b1));
}

__device__ __forceinline__ void mma_bf16_k8(float* c, unsigned a0, unsigned a1,
                                            unsigned b0) {
    asm volatile("mma.sync.aligned.m16n8k8.row.col.f32.bf16.bf16.f32 "
                 "{%0,%1,%2,%3}, {%4,%5}, {%6}, {%0,%1,%2,%3};"
                 : "+f"(c[0]), "+f"(c[1]), "+f"(c[2]), "+f"(c[3])
                 : "r"(a0), "r"(a1), "r"(b0));
}

__device__ __forceinline__ void cp_async16(void* smem_dst, const void* gmem_src, bool pred) {
    uint32_t s = (uint32_t)__cvta_generic_to_shared(smem_dst);
    int sz = pred ? 16 : 0;
    asm volatile("cp.async.cg.shared.global [%0], [%1], 16, %2;"
                 :: "r"(s), "l"(gmem_src), "r"(sz));
}
__device__ __forceinline__ void cp_commit() {
    asm volatile("cp.async.commit_group;");
}
template<int N>
__device__ __forceinline__ void cp_wait() {
    asm volatile("cp.async.wait_group %0;" :: "n"(N));
}

// ---------------- CSR build ----------------
__global__ __launch_bounds__(256) void deg_kernel(const int* __restrict__ edge,
                                                  const int* __restrict__ edge2) {
    int e = blockIdx.x * blockDim.x + threadIdx.x;
    if (e >= E_TOT) return;
    int src = (e < E1C) ? edge[e] : edge2[e - E1C];
    atomicAdd(&g_deg[src], 1);
}

__global__ __launch_bounds__(1024) void scan_kernel() {
    __shared__ int warp_sums[32];
    __shared__ int s_total;
    __shared__ int s_run;
    int t = threadIdx.x;
    int lane = t & 31, wid = t >> 5;
    if (t == 0) s_run = 0;
    __syncthreads();
    for (int base = 0; base < N_NODES; base += 1024) {
        int idx = base + t;
        int v = 0;
        if (idx < N_NODES) {
            v = g_deg[idx];
            g_deg[idx] = 0;
        }
        int incl = v;
        #pragma unroll
        for (int d = 1; d < 32; d <<= 1) {
            int n = __shfl_up_sync(0xffffffffu, incl, d);
            if (lane >= d) incl += n;
        }
        if (lane == 31) warp_sums[wid] = incl;
        __syncthreads();
        if (wid == 0) {
            int ws = warp_sums[lane];
            int wincl = ws;
            #pragma unroll
            for (int d = 1; d < 32; d <<= 1) {
                int n = __shfl_up_sync(0xffffffffu, wincl, d);
                if (lane >= d) wincl += n;
            }
            warp_sums[lane] = wincl - ws;
            if (lane == 31) s_total = wincl;
        }
        __syncthreads();
        int excl = s_run + warp_sums[wid] + incl - v;
        if (idx < N_NODES) { g_off[idx] = excl; g_cur[idx] = excl; }
        __syncthreads();
        if (t == 0) s_run += s_total;
        __syncthreads();
    }
    if (t == 0) g_off[N_NODES] = s_run;
}

__global__ __launch_bounds__(256) void fill_kernel(const int* __restrict__ edge,
                                                   const int* __restrict__ edge2) {
    int e = blockIdx.x * blockDim.x + threadIdx.x;
    if (e >= E_TOT) return;
    int src, dst;
    if (e < E1C) { src = edge[e]; dst = edge[E1C + e]; }
    else         { src = edge2[e - E1C]; dst = edge2[E2C + (e - E1C)]; }
    int pos = atomicAdd(&g_cur[src], 1);
    g_rec[pos] = make_int2(dst, e);
}

__global__ __launch_bounds__(256) void pack_kernel() {
    int i = blockIdx.x * blockDim.x + threadIdx.x;
    if (i >= E_TOT) return;
    int2 r = g_rec[i];
    float e = g_ee[r.y];
    g_rec3[i] = make_int4(r.x, r.y, __float_as_int(e), 0);
}

// ---------------- weights prep ----------------
__global__ __launch_bounds__(256) void transpose_kernel(const float* __restrict__ a) {
    int i = blockIdx.x * blockDim.x + threadIdx.x;
    if (i >= 300 * FDIM) return;
    int jp = i / FDIM;
    int n  = i % FDIM;
    float f0 = a[n * 600 + 2 * jp];
    float f1 = a[n * 600 + 2 * jp + 1];
    unsigned hi, lo;
    split_pack2(f0, f1, hi, lo);
    g_bqh[i] = hi;
    g_bql[i] = lo;
}

// pack x into pairs 0..99 of the unified A rows
__global__ __launch_bounds__(256) void pack_x_kernel(const float* __restrict__ x) {
    int i = blockIdx.x * blockDim.x + threadIdx.x;
    if (i >= N_NODES * 50) return;
    int m = i / 50, c = i % 50;
    float4 v = ((const float4*)x)[i];
    unsigned h0, l0, h1, l1;
    split_pack2(v.x, v.y, h0, l0);
    split_pack2(v.z, v.w, h1, l1);
    size_t o = (size_t)m * KP_ROW + 2 * c;
    *(uint2*)&g_aqh[o] = make_uint2(h0, h1);
    *(uint2*)&g_aql[o] = make_uint2(l0, l1);
}

__global__ __launch_bounds__(640) void vw_kernel(const float* __restrict__ a,
                                                 const float* __restrict__ a2,
                                                 const float* __restrict__ mw) {
    int j = threadIdx.x;
    if (j >= 600) return;
    float v = 0.f, w = 0.f;
    for (int o = 0; o < FDIM; o++) {
        float aj = a[o * 600 + j];
        v += aj * a2[o];
        w += aj * mw[o];
    }
    g_v[j] = v;
    g_w[j] = w;
}

__global__ __launch_bounds__(256) void pvec_kernel(const float* __restrict__ x) {
    __shared__ float4 sv[100];
    __shared__ float4 sw[100];
    int t = threadIdx.x;
    if (t < 100)       sv[t]       = ((const float4*)g_v)[t];
    else if (t < 200)  sw[t - 100] = ((const float4*)g_w)[t - 100];
    __syncthreads();

    int warp = t >> 5, lane = t & 31;
    int node = blockIdx.x * 8 + warp;
    if (node >= N_NODES) return;

    const float4* xr = (const float4*)x + (size_t)node * 50;
    float4 x0 = xr[lane];
    float4 x1 = (lane < 18) ? xr[32 + lane] : make_float4(0, 0, 0, 0);

    float p1  = dot4(x0, sv[lane])      + ((lane < 18) ? dot4(x1, sv[32 + lane]) : 0.f);
    float p2  = dot4(x0, sv[50 + lane]) + ((lane < 18) ? dot4(x1, sv[82 + lane]) : 0.f);
    float pm1 = dot4(x0, sw[lane])      + ((lane < 18) ? dot4(x1, sw[32 + lane]) : 0.f);
    float pm2 = dot4(x0, sw[50 + lane]) + ((lane < 18) ? dot4(x1, sw[82 + lane]) : 0.f);

    #pragma unroll
    for (int off = 16; off; off >>= 1) {
        p1  += __shfl_xor_sync(0xffffffffu, p1, off);
        p2  += __shfl_xor_sync(0xffffffffu, p2, off);
        pm1 += __shfl_xor_sync(0xffffffffu, pm1, off);
        pm2 += __shfl_xor_sync(0xffffffffu, pm2, off);
    }
    if (lane == 0) {
        g_p[node]               = p1;
        g_p[N_NODES + node]     = p2;
        g_p[2 * N_NODES + node] = pm1;
        g_p[3 * N_NODES + node] = pm2;
    }
}

// ---------------- phase 1: streaming edge scores (2 edges per warp) ----------------
__global__ __launch_bounds__(256) void score_kernel(const int* __restrict__ edge,
                                                    const float* __restrict__ emb1,
                                                    const int* __restrict__ edge2,
                                                    const float* __restrict__ emb2,
                                                    const float* __restrict__ mlp_b) {
    __shared__ float4 sv[50];
    __shared__ float4 sw[50];
    int t = threadIdx.x;
    if (t < 50)       sv[t]      = *(const float4*)&g_v[400 + t * 4];
    else if (t < 100) sw[t - 50] = *(const float4*)&g_w[400 + (t - 50) * 4];
    __syncthreads();

    int warp = t >> 5, lane = t & 31;
    int e0 = blockIdx.x * 16 + warp * 2;
    if (e0 >= E_TOT) return;
    bool hasB = (e0 + 1) < E_TOT;

    int srcA, dstA, srcB, dstB;
    const float4 *embA, *embB;
    if (e0 < E1C) {
        srcA = edge[e0]; dstA = edge[E1C + e0];
        embA = (const float4*)emb1 + (size_t)e0 * 50;
    } else {
        int r = e0 - E1C;
        srcA = edge2[r]; dstA = edge2[E2C + r];
        embA = (const float4*)emb2 + (size_t)r * 50;
    }
    int e1 = e0 + 1;
    if (hasB) {
        if (e1 < E1C) {
            srcB = edge[e1]; dstB = edge[E1C + e1];
            embB = (const float4*)emb1 + (size_t)e1 * 50;
        } else {
            int r = e1 - E1C;
            srcB = edge2[r]; dstB = edge2[E2C + r];
            embB = (const float4*)emb2 + (size_t)r * 50;
        }
    } else { srcB = srcA; dstB = dstA; embB = embA; }

    float4 svl = sv[lane];
    float4 swl = sw[lane];
    float4 a0 = embA[lane];
    float4 b0 = embB[lane];
    float4 a1 = (lane < 18) ? embA[32 + lane] : make_float4(0, 0, 0, 0);
    float4 b1 = (lane < 18) ? embB[32 + lane] : make_float4(0, 0, 0, 0);

    float q3A = dot4(a0, svl) + ((lane < 18) ? dot4(a1, sv[32 + lane]) : 0.f);
    float qmA = dot4(a0, swl) + ((lane < 18) ? dot4(a1, sw[32 + lane]) : 0.f);
    float q3B = dot4(b0, svl) + ((lane < 18) ? dot4(b1, sv[32 + lane]) : 0.f);
    float qmB = dot4(b0, swl) + ((lane < 18) ? dot4(b1, sw[32 + lane]) : 0.f);

    #pragma unroll
    for (int off = 16; off; off >>= 1) {
        q3A += __shfl_xor_sync(0xffffffffu, q3A, off);
        qmA += __shfl_xor_sync(0xffffffffu, qmA, off);
        q3B += __shfl_xor_sync(0xffffffffu, q3B, off);
        qmB += __shfl_xor_sync(0xffffffffu, qmB, off);
    }

    if (lane == 0) {
        float bias = mlp_b[0];
        float saA = g_p[srcA] + g_p[N_NODES + dstA] + q3A;
        float smA = g_p[2 * N_NODES + srcA] + g_p[3 * N_NODES + dstA] + qmA + bias;
        float lrA = (saA > 0.f) ? saA : ALPHA * saA;
        g_ee[e0] = __expf(-lrA * tanh_fast(smA) * (1.0f / (float)E_TOT));
        if (hasB) {
            float saB = g_p[srcB] + g_p[N_NODES + dstB] + q3B;
            float smB = g_p[2 * N_NODES + srcB] + g_p[3 * N_NODES + dstB] + qmB + bias;
            float lrB = (saB > 0.f) ? saB : ALPHA * saB;
            g_ee[e1] = __expf(-lrB * tanh_fast(smB) * (1.0f / (float)E_TOT));
        }
    }
}

// ---------------- fused K=600 bf16 3x tensor-core GEMM + epilogue ----------------
__device__ __forceinline__ void stage_tile(unsigned* Ah, unsigned* Al,
                                           unsigned* Bh, unsigned* Bl,
                                           int M, int row0, int kb, int t) {
    int kp0 = kb * KP_TILE;
    #pragma unroll
    for (int i = 0; i < 2; i++) {
        int idx = t + i * TG_THREADS;
        if (idx < 640) {
            int r = idx / 5, c4 = idx % 5;
            bool ok = (row0 + r) < M;
            size_t go = (size_t)(row0 + r) * KP_ROW + kp0 + c4 * 4;
            cp_async16(Ah + r * A_STRIDE + c4 * 4, g_aqh + go, ok);
            cp_async16(Al + r * A_STRIDE + c4 * 4, g_aql + go, ok);
        }
    }
    const unsigned* sH = g_bqh + (size_t)kp0 * FDIM;
    const unsigned* sL = g_bql + (size_t)kp0 * FDIM;
    #pragma unroll
    for (int i = 0; i < 2; i++) {
        int idx = t + i * TG_THREADS;
        if (idx < 1000) {
            int row = idx / 50, c4 = idx % 50;
            cp_async16(Bh + row * B_STRIDE + c4 * 4, sH + idx * 4, true);
            cp_async16(Bl + row * B_STRIDE + c4 * 4, sL + idx * 4, true);
        }
    }
}

__global__ void __launch_bounds__(TG_THREADS, 1)
tgemm_kernel(int M, float* __restrict__ fout) {
    extern __shared__ unsigned smu_[];
    unsigned* Ah[2] = { smu_, smu_ + A_BUFU };
    unsigned* Al[2] = { smu_ + 2 * A_BUFU, smu_ + 3 * A_BUFU };
    unsigned* Bh[2] = { smu_ + 4 * A_BUFU, smu_ + 4 * A_BUFU + B_BUFU };
    unsigned* Bl[2] = { smu_ + 4 * A_BUFU + 2 * B_BUFU, smu_ + 4 * A_BUFU + 3 * B_BUFU };

    int row0 = blockIdx.x * BM;
    int t = threadIdx.x;
    int warp = t >> 5, lane = t & 31;
    int mg = warp >> 2;
    int ng = warp & 3;
    int n0 = ng * 56;
    int m0w = mg * 32;
    int lr = lane >> 2;
    int lc = lane & 3;

    float acc[2][7][4];
    #pragma unroll
    for (int a_ = 0; a_ < 2; a_++)
        #pragma unroll
        for (int b_ = 0; b_ < 7; b_++)
            #pragma unroll
            for (int c_ = 0; c_ < 4; c_++) acc[a_][b_][c_] = 0.f;

    stage_tile(Ah[0], Al[0], Bh[0], Bl[0], M, row0, 0, t);
    cp_commit();

    for (int kb = 0; kb < NKB; kb++) {
        int cur = kb & 1;
        if (kb + 1 < NKB) {
            stage_tile(Ah[cur ^ 1], Al[cur ^ 1], Bh[cur ^ 1], Bl[cur ^ 1],
                       M, row0, kb + 1, t);
            cp_commit();
            cp_wait<1>();
        } else {
            cp_wait<0>();
        }
        __syncthreads();

        const unsigned* Ach = Ah[cur];
        const unsigned* Acl = Al[cur];
        const unsigned* Bch = Bh[cur];
        const unsigned* Bcl = Bl[cur];

        #pragma unroll
        for (int st = 0; st < 2; st++) {
            int kpb = st * 8;
            unsigned ah[2][4], al[2][4];
            #pragma unroll
            for (int mt = 0; mt < 2; mt++) {
                int mrow = m0w + mt * 16 + lr;
                ah[mt][0] = Ach[mrow * A_STRIDE + kpb + lc];
                ah[mt][1] = Ach[(mrow + 8) * A_STRIDE + kpb + lc];
                ah[mt][2] = Ach[mrow * A_STRIDE + kpb + lc + 4];
                ah[mt][3] = Ach[(mrow + 8) * A_STRIDE + kpb + lc + 4];
                al[mt][0] = Acl[mrow * A_STRIDE + kpb + lc];
                al[mt][1] = Acl[(mrow + 8) * A_STRIDE + kpb + lc];
                al[mt][2] = Acl[mrow * A_STRIDE + kpb + lc + 4];
                al[mt][3] = Acl[(mrow + 8) * A_STRIDE + kpb + lc + 4];
            }
            #pragma unroll
            for (int nt = 0; nt < 7; nt++) {
                int nc = n0 + nt * 8 + lr;
                unsigned bh0 = Bch[(kpb + lc) * B_STRIDE + nc];
                unsigned bh1 = Bch[(kpb + lc + 4) * B_STRIDE + nc];
                unsigned bl0 = Bcl[(kpb + lc) * B_STRIDE + nc];
                unsigned bl1 = Bcl[(kpb + lc + 4) * B_STRIDE + nc];
                #pragma unroll
                for (int mt = 0; mt < 2; mt++) {
                    mma_bf16_k16(acc[mt][nt], ah[mt], bh0, bh1);
                    mma_bf16_k16(acc[mt][nt], ah[mt], bl0, bl1);
                    mma_bf16_k16(acc[mt][nt], al[mt], bh0, bh1);
                }
            }
        }
        {
            unsigned ah8[2][2], al8[2][2];
            #pragma unroll
            for (int mt = 0; mt < 2; mt++) {
                int mrow = m0w + mt * 16 + lr;
                ah8[mt][0] = Ach[mrow * A_STRIDE + 16 + lc];
                ah8[mt][1] = Ach[(mrow + 8) * A_STRIDE + 16 + lc];
                al8[mt][0] = Acl[mrow * A_STRIDE + 16 + lc];
                al8[mt][1] = Acl[(mrow + 8) * A_STRIDE + 16 + lc];
            }
            #pragma unroll
            for (int nt = 0; nt < 7; nt++) {
                int nc = n0 + nt * 8 + lr;
                unsigned bh0 = Bch[(16 + lc) * B_STRIDE + nc];
                unsigned bl0 = Bcl[(16 + lc) * B_STRIDE + nc];
                #pragma unroll
                for (int mt = 0; mt < 2; mt++) {
                    mma_bf16_k8(acc[mt][nt], ah8[mt][0], ah8[mt][1], bh0);
                    mma_bf16_k8(acc[mt][nt], ah8[mt][0], ah8[mt][1], bl0);
                    mma_bf16_k8(acc[mt][nt], al8[mt][0], al8[mt][1], bh0);
                }
            }
        }
        __syncthreads();
    }

    // epilogue: out = rs==0 ? 0 : elu(acc)
    #pragma unroll
    for (int mt = 0; mt < 2; mt++) {
        #pragma unroll
        for (int h = 0; h < 2; h++) {
            int r = row0 + m0w + mt * 16 + lr + 8 * h;
            if (r >= M) continue;
            float rs = g_rs[r];
            if (rs == 0.f) {
                #pragma unroll
                for (int nt = 0; nt < 7; nt++) {
                    int col = n0 + nt * 8 + 2 * lc;
                    if (col >= FDIM) continue;
                    *(float2*)(fout + (size_t)r * FDIM + col) = make_float2(0.f, 0.f);
                }
            } else {
                #pragma unroll
                for (int nt = 0; nt < 7; nt++) {
                    int col = n0 + nt * 8 + 2 * lc;
                    if (col >= FDIM) continue;
                    float v0 = acc[mt][nt][2 * h + 0];
                    float v1 = acc[mt][nt][2 * h + 1];
                    v0 = (v0 > 0.f) ? v0 : (expf(v0) - 1.f);
                    v1 = (v1 > 0.f) ? v1 : (expf(v1) - 1.f);
                    *(float2*)(fout + (size_t)r * FDIM + col) = make_float2(v0, v1);
                }
            }
        }
    }
}

// ---------------- phase 2: x-space role-split gather ----------------
// role 0: G = sum ee*emb -> *inv -> packed pairs 200..299 ; writes g_rs
// role 1: ACCx = sum ee*x[dst] -> *inv -> packed pairs 100..199
__global__ __launch_bounds__(256) void gather_kernel(const float* __restrict__ x,
                                                     const float* __restrict__ emb1,
                                                     const float* __restrict__ emb2) {
    int t = threadIdx.x;
    int warp = t >> 5, lane = t & 31;
    int node = blockIdx.x * 4 + (warp >> 1);
    int role = warp & 1;
    if (node >= N_NODES) return;

    int beg = g_off[node];
    int end = g_off[node + 1];

    float4 a0 = make_float4(0, 0, 0, 0), a1 = a0;
    float rs = 0.f;

    for (int base = beg; base < end; base += 32) {
        int cnt = min(32, end - base);
        int4 rr = (lane < cnt) ? g_rec3[base + lane] : make_int4(0, 0, 0, 0);

        int j = 0;
        for (; j + 4 <= cnt; j += 4) {
            const float4* p[4];
            float e[4];
            #pragma unroll
            for (int k = 0; k < 4; k++) {
                int dstk = __shfl_sync(0xffffffffu, rr.x, j + k);
                int eidk = __shfl_sync(0xffffffffu, rr.y, j + k);
                e[k] = __int_as_float(__shfl_sync(0xffffffffu, rr.z, j + k));
                if (role == 0) {
                    p[k] = (eidk < E1C) ? (const float4*)emb1 + (size_t)eidk * 50
                                        : (const float4*)emb2 + (size_t)(eidk - E1C) * 50;
                } else {
                    p[k] = (const float4*)x + (size_t)dstk * 50;
                }
            }
            float4 v[4], u[4];
            #pragma unroll
            for (int k = 0; k < 4; k++) v[k] = p[k][lane];
            if (lane < 18) {
                #pragma unroll
                for (int k = 0; k < 4; k++) u[k] = p[k][32 + lane];
            }
            #pragma unroll
            for (int k = 0; k < 4; k++) {
                rs += e[k];
                a0.x += e[k] * v[k].x; a0.y += e[k] * v[k].y;
                a0.z += e[k] * v[k].z; a0.w += e[k] * v[k].w;
            }
            if (lane < 18) {
                #pragma unroll
                for (int k = 0; k < 4; k++) {
                    a1.x += e[k] * u[k].x; a1.y += e[k] * u[k].y;
                    a1.z += e[k] * u[k].z; a1.w += e[k] * u[k].w;
                }
            }
        }
        for (; j < cnt; j++) {
            int dst0 = __shfl_sync(0xffffffffu, rr.x, j);
            int eid0 = __shfl_sync(0xffffffffu, rr.y, j);
            float e0 = __int_as_float(__shfl_sync(0xffffffffu, rr.z, j));
            const float4* p0;
            if (role == 0) {
                p0 = (eid0 < E1C) ? (const float4*)emb1 + (size_t)eid0 * 50
                                  : (const float4*)emb2 + (size_t)(eid0 - E1C) * 50;
            } else {
                p0 = (const float4*)x + (size_t)dst0 * 50;
            }
            float4 v0 = p0[lane];
            rs += e0;
            a0.x += e0 * v0.x; a0.y += e0 * v0.y; a0.z += e0 * v0.z; a0.w += e0 * v0.w;
            if (lane < 18) {
                float4 u0 = p0[32 + lane];
                a1.x += e0 * u0.x; a1.y += e0 * u0.y; a1.z += e0 * u0.z; a1.w += e0 * u0.w;
            }
        }
    }

    float inv = (rs == 0.f) ? 0.f : 1.f / rs;
    a0.x *= inv; a0.y *= inv; a0.z *= inv; a0.w *= inv;
    a1.x *= inv; a1.y *= inv; a1.z *= inv; a1.w *= inv;

    int colbase = (role == 0) ? 200 : 100;
    unsigned h0, l0, h1, l1;
    split_pack2(a0.x, a0.y, h0, l0);
    split_pack2(a0.z, a0.w, h1, l1);
    size_t o = (size_t)node * KP_ROW + colbase + 2 * lane;
    *(uint2*)&g_aqh[o] = make_uint2(h0, h1);
    *(uint2*)&g_aql[o] = make_uint2(l0, l1);
    if (lane < 18) {
        split_pack2(a1.x, a1.y, h0, l0);
        split_pack2(a1.z, a1.w, h1, l1);
        size_t o2 = (size_t)node * KP_ROW + colbase + 64 + 2 * lane;
        *(uint2*)&g_aqh[o2] = make_uint2(h0, h1);
        *(uint2*)&g_aql[o2] = make_uint2(l0, l1);
    }
    if (role == 0 && lane == 0) g_rs[node] = rs;
}

// ---- streams/events created once at load time ----
struct GraphResources {
    cudaStream_t s1, s2;
    cudaEvent_t evStart, evT, evPX, evCSR;
    GraphResources() {
        cudaStreamCreateWithFlags(&s1, cudaStreamNonBlocking);
        cudaStreamCreateWithFlags(&s2, cudaStreamNonBlocking);
        cudaEventCreateWithFlags(&evStart, cudaEventDisableTiming);
        cudaEventCreateWithFlags(&evT, cudaEventDisableTiming);
        cudaEventCreateWithFlags(&evPX, cudaEventDisableTiming);
        cudaEventCreateWithFlags(&evCSR, cudaEventDisableTiming);
    }
};
static GraphResources g_gr;

extern "C" void kernel_launch(void* const* d_in, const int* in_sizes, int n_in,
                              void* d_out, int out_size) {
    const float* x    = (const float*)d_in[0];
    const int*   edge = (const int*)  d_in[1];
    const float* ee1  = (const float*)d_in[2];
    const int*   edg2 = (const int*)  d_in[3];
    const float* ee2  = (const float*)d_in[4];
    const float* a    = (const float*)d_in[5];
    const float* a2   = (const float*)d_in[6];
    const float* mw   = (const float*)d_in[7];
    const float* mb   = (const float*)d_in[8];
    float* out = (float*)d_out;

    cudaFuncSetAttribute(tgemm_kernel, cudaFuncAttributeMaxDynamicSharedMemorySize, SMEM_BYTES);

    int ggrid = (N_NODES + BM - 1) / BM;
    cudaStream_t s0 = 0;

    cudaEventRecord(g_gr.evStart, s0);

    // s0: prep, then score
    transpose_kernel<<<(300 * FDIM + 255) / 256, 256, 0, s0>>>(a);
    vw_kernel<<<1, 640, 0, s0>>>(a, a2, mw);
    pvec_kernel<<<N_NODES / 8, 256, 0, s0>>>(x);
    score_kernel<<<(E_TOT + 15) / 16, 256, 0, s0>>>(edge, ee1, edg2, ee2, mb);

    // s2: pack_x (independent; needed only by final GEMM)
    cudaStreamWaitEvent(g_gr.s2, g_gr.evStart, 0);
    pack_x_kernel<<<(N_NODES * 50 + 255) / 256, 256, 0, g_gr.s2>>>(x);
    cudaEventRecord(g_gr.evPX, g_gr.s2);

    // s1: CSR build
    cudaStreamWaitEvent(g_gr.s1, g_gr.evStart, 0);
    deg_kernel<<<(E_TOT + 255) / 256, 256, 0, g_gr.s1>>>(edge, edg2);
    scan_kernel<<<1, 1024, 0, g_gr.s1>>>();
    fill_kernel<<<(E_TOT + 255) / 256, 256, 0, g_gr.s1>>>(edge, edg2);
    cudaEventRecord(g_gr.evCSR, g_gr.s1);

    // s0: pack recs (needs score + CSR), then gather (no GEMM dependency!)
    cudaStreamWaitEvent(s0, g_gr.evCSR, 0);
    pack_kernel<<<(E_TOT + 255) / 256, 256, 0, s0>>>();
    gather_kernel<<<(N_NODES + 3) / 4, 256, 0, s0>>>(x, ee1, ee2);

    // fused final GEMM (needs gather on s0 + pack_x)
    cudaStreamWaitEvent(s0, g_gr.evPX, 0);
    tgemm_kernel<<<ggrid, TG_THREADS, SMEM_BYTES, s0>>>(N_NODES, out);
}

// round 16
// speedup vs baseline: 1.2364x; 1.0181x over previous
#include <cuda_runtime.h>
#include <cuda_bf16.h>
#include <math.h>
#include <stdint.h>

#define N_NODES 50000
#define FDIM    200
#define E1C     400000
#define E2C     100000
#define E_TOT   500000
#define ALPHA   0.2f

// fused K=600 bf16 3x GEMM: 512 threads / 16 warps, 15 K-slabs, 3-stage pipeline
#define BM 128
#define KP_TILE 20
#define NKB 15
#define KP_ROW 300
#define A_STRIDE 20
#define B_STRIDE 200
#define A_BUFU (BM * A_STRIDE)
#define B_BUFU (KP_TILE * B_STRIDE + 64)
#define SMEM_UINTS (6 * A_BUFU + 6 * B_BUFU)
#define SMEM_BYTES (SMEM_UINTS * 4)
#define TG_THREADS 512

// ---- device scratch ----
__device__ float g_rs[N_NODES];
__device__ float g_p[4 * N_NODES];
__device__ float g_v[600];
__device__ float g_w[600];
__device__ unsigned g_bqh[300 * FDIM];
__device__ unsigned g_bql[300 * FDIM];
__device__ unsigned g_aqh[(size_t)N_NODES * KP_ROW];
__device__ unsigned g_aql[(size_t)N_NODES * KP_ROW];
__device__ float g_ee[E_TOT];
__device__ int  g_deg[N_NODES];
__device__ int  g_off[N_NODES + 1];
__device__ int  g_cur[N_NODES];
__device__ int2 g_rec[E_TOT];
__device__ int4 g_rec3[E_TOT];

__device__ __forceinline__ float dot4(float4 a, float4 b) {
    return a.x * b.x + a.y * b.y + a.z * b.z + a.w * b.w;
}

__device__ __forceinline__ float tanh_fast(float x) {
    float y;
    asm("tanh.approx.f32 %0, %1;" : "=f"(y) : "f"(x));
    return y;
}

__device__ __forceinline__ void split_pack2(float f0, float f1,
                                            unsigned& hi, unsigned& lo) {
    __nv_bfloat162 h = __float22bfloat162_rn(make_float2(f0, f1));
    hi = *reinterpret_cast<unsigned*>(&h);
    float l0 = f0 - __bfloat162float(h.x);
    float l1 = f1 - __bfloat162float(h.y);
    __nv_bfloat162 l = __float22bfloat162_rn(make_float2(l0, l1));
    lo = *reinterpret_cast<unsigned*>(&l);
}

__device__ __forceinline__ void mma_bf16_k16(float* c, const unsigned* a,
                                             unsigned b0, unsigned b1) {
    asm volatile("mma.sync.aligned.m16n8k16.row.col.f32.bf16.bf16.f32 "
                 "{%0,%1,%2,%3}, {%4,%5,%6,%7}, {%8,%9}, {%0,%1,%2,%3};"
                 : "+f"(c[0]), "+f"(c[1]), "+f"(c[2]), "+f"(c[3])
                 : "r"(a[0]), "r"(a[1]), "r"(a[2]), "r"(a[3]), "r"(b0), "r"(b1));
}

__device__ __forceinline__ void mma_bf16_k8(float* c, unsigned a0, unsigned a1,
                                            unsigned b0) {
    asm volatile("mma.sync.aligned.m16n8k8.row.col.f32.bf16.bf16.f32 "
                 "{%0,%1,%2,%3}, {%4,%5}, {%6}, {%0,%1,%2,%3};"
                 : "+f"(c[0]), "+f"(c[1]), "+f"(c[2]), "+f"(c[3])
                 : "r"(a0), "r"(a1), "r"(b0));
}

__device__ __forceinline__ void cp_async16(void* smem_dst, const void* gmem_src, bool pred) {
    uint32_t s = (uint32_t)__cvta_generic_to_shared(smem_dst);
    int sz = pred ? 16 : 0;
    asm volatile("cp.async.cg.shared.global [%0], [%1], 16, %2;"
                 :: "r"(s), "l"(gmem_src), "r"(sz));
}
__device__ __forceinline__ void cp_commit() {
    asm volatile("cp.async.commit_group;");
}
template<int N>
__device__ __forceinline__ void cp_wait() {
    asm volatile("cp.async.wait_group %0;" :: "n"(N));
}

// ---------------- CSR build ----------------
__global__ __launch_bounds__(256) void deg_kernel(const int* __restrict__ edge,
                                                  const int* __restrict__ edge2) {
    int e = blockIdx.x * blockDim.x + threadIdx.x;
    if (e >= E_TOT) return;
    int src = (e < E1C) ? edge[e] : edge2[e - E1C];
    atomicAdd(&g_deg[src], 1);
}

__global__ __launch_bounds__(1024) void scan_kernel() {
    __shared__ int warp_sums[32];
    __shared__ int s_total;
    __shared__ int s_run;
    int t = threadIdx.x;
    int lane = t & 31, wid = t >> 5;
    if (t == 0) s_run = 0;
    __syncthreads();
    for (int base = 0; base < N_NODES; base += 1024) {
        int idx = base + t;
        int v = 0;
        if (idx < N_NODES) {
            v = g_deg[idx];
            g_deg[idx] = 0;
        }
        int incl = v;
        #pragma unroll
        for (int d = 1; d < 32; d <<= 1) {
            int n = __shfl_up_sync(0xffffffffu, incl, d);
            if (lane >= d) incl += n;
        }
        if (lane == 31) warp_sums[wid] = incl;
        __syncthreads();
        if (wid == 0) {
            int ws = warp_sums[lane];
            int wincl = ws;
            #pragma unroll
            for (int d = 1; d < 32; d <<= 1) {
                int n = __shfl_up_sync(0xffffffffu, wincl, d);
                if (lane >= d) wincl += n;
            }
            warp_sums[lane] = wincl - ws;
            if (lane == 31) s_total = wincl;
        }
        __syncthreads();
        int excl = s_run + warp_sums[wid] + incl - v;
        if (idx < N_NODES) { g_off[idx] = excl; g_cur[idx] = excl; }
        __syncthreads();
        if (t == 0) s_run += s_total;
        __syncthreads();
    }
    if (t == 0) g_off[N_NODES] = s_run;
}

__global__ __launch_bounds__(256) void fill_kernel(const int* __restrict__ edge,
                                                   const int* __restrict__ edge2) {
    int e = blockIdx.x * blockDim.x + threadIdx.x;
    if (e >= E_TOT) return;
    int src, dst;
    if (e < E1C) { src = edge[e]; dst = edge[E1C + e]; }
    else         { src = edge2[e - E1C]; dst = edge2[E2C + (e - E1C)]; }
    int pos = atomicAdd(&g_cur[src], 1);
    g_rec[pos] = make_int2(dst, e);
}

__global__ __launch_bounds__(256) void pack_kernel() {
    int i = blockIdx.x * blockDim.x + threadIdx.x;
    if (i >= E_TOT) return;
    int2 r = g_rec[i];
    float e = g_ee[r.y];
    g_rec3[i] = make_int4(r.x, r.y, __float_as_int(e), 0);
}

// ---------------- weights prep ----------------
__global__ __launch_bounds__(256) void transpose_kernel(const float* __restrict__ a) {
    int i = blockIdx.x * blockDim.x + threadIdx.x;
    if (i >= 300 * FDIM) return;
    int jp = i / FDIM;
    int n  = i % FDIM;
    float f0 = a[n * 600 + 2 * jp];
    float f1 = a[n * 600 + 2 * jp + 1];
    unsigned hi, lo;
    split_pack2(f0, f1, hi, lo);
    g_bqh[i] = hi;
    g_bql[i] = lo;
}

__global__ __launch_bounds__(256) void pack_x_kernel(const float* __restrict__ x) {
    int i = blockIdx.x * blockDim.x + threadIdx.x;
    if (i >= N_NODES * 50) return;
    int m = i / 50, c = i % 50;
    float4 v = ((const float4*)x)[i];
    unsigned h0, l0, h1, l1;
    split_pack2(v.x, v.y, h0, l0);
    split_pack2(v.z, v.w, h1, l1);
    size_t o = (size_t)m * KP_ROW + 2 * c;
    *(uint2*)&g_aqh[o] = make_uint2(h0, h1);
    *(uint2*)&g_aql[o] = make_uint2(l0, l1);
}

__global__ __launch_bounds__(640) void vw_kernel(const float* __restrict__ a,
                                                 const float* __restrict__ a2,
                                                 const float* __restrict__ mw) {
    int j = threadIdx.x;
    if (j >= 600) return;
    float v = 0.f, w = 0.f;
    for (int o = 0; o < FDIM; o++) {
        float aj = a[o * 600 + j];
        v += aj * a2[o];
        w += aj * mw[o];
    }
    g_v[j] = v;
    g_w[j] = w;
}

__global__ __launch_bounds__(256) void pvec_kernel(const float* __restrict__ x) {
    __shared__ float4 sv[100];
    __shared__ float4 sw[100];
    int t = threadIdx.x;
    if (t < 100)       sv[t]       = ((const float4*)g_v)[t];
    else if (t < 200)  sw[t - 100] = ((const float4*)g_w)[t - 100];
    __syncthreads();

    int warp = t >> 5, lane = t & 31;
    int node = blockIdx.x * 8 + warp;
    if (node >= N_NODES) return;

    const float4* xr = (const float4*)x + (size_t)node * 50;
    float4 x0 = xr[lane];
    float4 x1 = (lane < 18) ? xr[32 + lane] : make_float4(0, 0, 0, 0);

    float p1  = dot4(x0, sv[lane])      + ((lane < 18) ? dot4(x1, sv[32 + lane]) : 0.f);
    float p2  = dot4(x0, sv[50 + lane]) + ((lane < 18) ? dot4(x1, sv[82 + lane]) : 0.f);
    float pm1 = dot4(x0, sw[lane])      + ((lane < 18) ? dot4(x1, sw[32 + lane]) : 0.f);
    float pm2 = dot4(x0, sw[50 + lane]) + ((lane < 18) ? dot4(x1, sw[82 + lane]) : 0.f);

    #pragma unroll
    for (int off = 16; off; off >>= 1) {
        p1  += __shfl_xor_sync(0xffffffffu, p1, off);
        p2  += __shfl_xor_sync(0xffffffffu, p2, off);
        pm1 += __shfl_xor_sync(0xffffffffu, pm1, off);
        pm2 += __shfl_xor_sync(0xffffffffu, pm2, off);
    }
    if (lane == 0) {
        g_p[node]               = p1;
        g_p[N_NODES + node]     = p2;
        g_p[2 * N_NODES + node] = pm1;
        g_p[3 * N_NODES + node] = pm2;
    }
}

// ---------------- phase 1: streaming edge scores (2 edges per warp) ----------------
__global__ __launch_bounds__(256) void score_kernel(const int* __restrict__ edge,
                                                    const float* __restrict__ emb1,
                                                    const int* __restrict__ edge2,
                                                    const float* __restrict__ emb2,
                                                    const float* __restrict__ mlp_b) {
    __shared__ float4 sv[50];
    __shared__ float4 sw[50];
    int t = threadIdx.x;
    if (t < 50)       sv[t]      = *(const float4*)&g_v[400 + t * 4];
    else if (t < 100) sw[t - 50] = *(const float4*)&g_w[400 + (t - 50) * 4];
    __syncthreads();

    int warp = t >> 5, lane = t & 31;
    int e0 = blockIdx.x * 16 + warp * 2;
    if (e0 >= E_TOT) return;
    bool hasB = (e0 + 1) < E_TOT;

    int srcA, dstA, srcB, dstB;
    const float4 *embA, *embB;
    if (e0 < E1C) {
        srcA = edge[e0]; dstA = edge[E1C + e0];
        embA = (const float4*)emb1 + (size_t)e0 * 50;
    } else {
        int r = e0 - E1C;
        srcA = edge2[r]; dstA = edge2[E2C + r];
        embA = (const float4*)emb2 + (size_t)r * 50;
    }
    int e1 = e0 + 1;
    if (hasB) {
        if (e1 < E1C) {
            srcB = edge[e1]; dstB = edge[E1C + e1];
            embB = (const float4*)emb1 + (size_t)e1 * 50;
        } else {
            int r = e1 - E1C;
            srcB = edge2[r]; dstB = edge2[E2C + r];
            embB = (const float4*)emb2 + (size_t)r * 50;
        }
    } else { srcB = srcA; dstB = dstA; embB = embA; }

    float4 svl = sv[lane];
    float4 swl = sw[lane];
    float4 a0 = embA[lane];
    float4 b0 = embB[lane];
    float4 a1 = (lane < 18) ? embA[32 + lane] : make_float4(0, 0, 0, 0);
    float4 b1 = (lane < 18) ? embB[32 + lane] : make_float4(0, 0, 0, 0);

    float q3A = dot4(a0, svl) + ((lane < 18) ? dot4(a1, sv[32 + lane]) : 0.f);
    float qmA = dot4(a0, swl) + ((lane < 18) ? dot4(a1, sw[32 + lane]) : 0.f);
    float q3B = dot4(b0, svl) + ((lane < 18) ? dot4(b1, sv[32 + lane]) : 0.f);
    float qmB = dot4(b0, swl) + ((lane < 18) ? dot4(b1, sw[32 + lane]) : 0.f);

    #pragma unroll
    for (int off = 16; off; off >>= 1) {
        q3A += __shfl_xor_sync(0xffffffffu, q3A, off);
        qmA += __shfl_xor_sync(0xffffffffu, qmA, off);
        q3B += __shfl_xor_sync(0xffffffffu, q3B, off);
        qmB += __shfl_xor_sync(0xffffffffu, qmB, off);
    }

    if (lane == 0) {
        float bias = mlp_b[0];
        float saA = g_p[srcA] + g_p[N_NODES + dstA] + q3A;
        float smA = g_p[2 * N_NODES + srcA] + g_p[3 * N_NODES + dstA] + qmA + bias;
        float lrA = (saA > 0.f) ? saA : ALPHA * saA;
        g_ee[e0] = __expf(-lrA * tanh_fast(smA) * (1.0f / (float)E_TOT));
        if (hasB) {
            float saB = g_p[srcB] + g_p[N_NODES + dstB] + q3B;
            float smB = g_p[2 * N_NODES + srcB] + g_p[3 * N_NODES + dstB] + qmB + bias;
            float lrB = (saB > 0.f) ? saB : ALPHA * saB;
            g_ee[e1] = __expf(-lrB * tanh_fast(smB) * (1.0f / (float)E_TOT));
        }
    }
}

// ---------------- fused K=600 GEMM, 3-stage pipeline + epilogue ----------------
__device__ __forceinline__ void stage_tile(unsigned* Ah, unsigned* Al,
                                           unsigned* Bh, unsigned* Bl,
                                           int M, int row0, int kb, int t) {
    int kp0 = kb * KP_TILE;
    #pragma unroll
    for (int i = 0; i < 2; i++) {
        int idx = t + i * TG_THREADS;
        if (idx < 640) {
            int r = idx / 5, c4 = idx % 5;
            bool ok = (row0 + r) < M;
            size_t go = (size_t)(row0 + r) * KP_ROW + kp0 + c4 * 4;
            cp_async16(Ah + r * A_STRIDE + c4 * 4, g_aqh + go, ok);
            cp_async16(Al + r * A_STRIDE + c4 * 4, g_aql + go, ok);
        }
    }
    const unsigned* sH = g_bqh + (size_t)kp0 * FDIM;
    const unsigned* sL = g_bql + (size_t)kp0 * FDIM;
    #pragma unroll
    for (int i = 0; i < 2; i++) {
        int idx = t + i * TG_THREADS;
        if (idx < 1000) {
            int row = idx / 50, c4 = idx % 50;
            cp_async16(Bh + row * B_STRIDE + c4 * 4, sH + idx * 4, true);
            cp_async16(Bl + row * B_STRIDE + c4 * 4, sL + idx * 4, true);
        }
    }
}

__global__ void __launch_bounds__(TG_THREADS, 1)
tgemm_kernel(int M, float* __restrict__ fout) {
    extern __shared__ unsigned smu_[];
    unsigned* Ah[3] = { smu_, smu_ + A_BUFU, smu_ + 2 * A_BUFU };
    unsigned* Al[3] = { smu_ + 3 * A_BUFU, smu_ + 4 * A_BUFU, smu_ + 5 * A_BUFU };
    unsigned* bbase = smu_ + 6 * A_BUFU;
    unsigned* Bh[3] = { bbase, bbase + B_BUFU, bbase + 2 * B_BUFU };
    unsigned* Bl[3] = { bbase + 3 * B_BUFU, bbase + 4 * B_BUFU, bbase + 5 * B_BUFU };

    int row0 = blockIdx.x * BM;
    int t = threadIdx.x;
    int warp = t >> 5, lane = t & 31;
    int mg = warp >> 2;
    int ng = warp & 3;
    int n0 = ng * 56;
    int m0w = mg * 32;
    int lr = lane >> 2;
    int lc = lane & 3;

    float acc[2][7][4];
    #pragma unroll
    for (int a_ = 0; a_ < 2; a_++)
        #pragma unroll
        for (int b_ = 0; b_ < 7; b_++)
            #pragma unroll
            for (int c_ = 0; c_ < 4; c_++) acc[a_][b_][c_] = 0.f;

    stage_tile(Ah[0], Al[0], Bh[0], Bl[0], M, row0, 0, t);
    cp_commit();
    stage_tile(Ah[1], Al[1], Bh[1], Bl[1], M, row0, 1, t);
    cp_commit();

    for (int kb = 0; kb < NKB; kb++) {
        int cur = kb % 3;
        cp_wait<1>();
        __syncthreads();

        // prefetch slab kb+2 into buffer (kb+2)%3 — freed by the barrier above
        if (kb + 2 < NKB) {
            int nxt = (kb + 2) % 3;
            stage_tile(Ah[nxt], Al[nxt], Bh[nxt], Bl[nxt], M, row0, kb + 2, t);
            cp_commit();
        }

        const unsigned* Ach = Ah[cur];
        const unsigned* Acl = Al[cur];
        const unsigned* Bch = Bh[cur];
        const unsigned* Bcl = Bl[cur];

        #pragma unroll
        for (int st = 0; st < 2; st++) {
            int kpb = st * 8;
            unsigned ah[2][4], al[2][4];
            #pragma unroll
            for (int mt = 0; mt < 2; mt++) {
                int mrow = m0w + mt * 16 + lr;
                ah[mt][0] = Ach[mrow * A_STRIDE + kpb + lc];
                ah[mt][1] = Ach[(mrow + 8) * A_STRIDE + kpb + lc];
                ah[mt][2] = Ach[mrow * A_STRIDE + kpb + lc + 4];
                ah[mt][3] = Ach[(mrow + 8) * A_STRIDE + kpb + lc + 4];
                al[mt][0] = Acl[mrow * A_STRIDE + kpb + lc];
                al[mt][1] = Acl[(mrow + 8) * A_STRIDE + kpb + lc];
                al[mt][2] = Acl[mrow * A_STRIDE + kpb + lc + 4];
                al[mt][3] = Acl[(mrow + 8) * A_STRIDE + kpb + lc + 4];
            }
            #pragma unroll
            for (int nt = 0; nt < 7; nt++) {
                int nc = n0 + nt * 8 + lr;
                unsigned bh0 = Bch[(kpb + lc) * B_STRIDE + nc];
                unsigned bh1 = Bch[(kpb + lc + 4) * B_STRIDE + nc];
                unsigned bl0 = Bcl[(kpb + lc) * B_STRIDE + nc];
                unsigned bl1 = Bcl[(kpb + lc + 4) * B_STRIDE + nc];
                #pragma unroll
                for (int mt = 0; mt < 2; mt++) {
                    mma_bf16_k16(acc[mt][nt], ah[mt], bh0, bh1);
                    mma_bf16_k16(acc[mt][nt], ah[mt], bl0, bl1);
                    mma_bf16_k16(acc[mt][nt], al[mt], bh0, bh1);
                }
            }
        }
        {
            unsigned ah8[2][2], al8[2][2];
            #pragma unroll
            for (int mt = 0; mt < 2; mt++) {
                int mrow = m0w + mt * 16 + lr;
                ah8[mt][0] = Ach[mrow * A_STRIDE + 16 + lc];
                ah8[mt][1] = Ach[(mrow + 8) * A_STRIDE + 16 + lc];
                al8[mt][0] = Acl[mrow * A_STRIDE + 16 + lc];
                al8[mt][1] = Acl[(mrow + 8) * A_STRIDE + 16 + lc];
            }
            #pragma unroll
            for (int nt = 0; nt < 7; nt++) {
                int nc = n0 + nt * 8 + lr;
                unsigned bh0 = Bch[(16 + lc) * B_STRIDE + nc];
                unsigned bl0 = Bcl[(16 + lc) * B_STRIDE + nc];
                #pragma unroll
                for (int mt = 0; mt < 2; mt++) {
                    mma_bf16_k8(acc[mt][nt], ah8[mt][0], ah8[mt][1], bh0);
                    mma_bf16_k8(acc[mt][nt], ah8[mt][0], ah8[mt][1], bl0);
                    mma_bf16_k8(acc[mt][nt], al8[mt][0], al8[mt][1], bh0);
                }
            }
        }
    }

    // epilogue: out = rs==0 ? 0 : elu(acc)
    #pragma unroll
    for (int mt = 0; mt < 2; mt++) {
        #pragma unroll
        for (int h = 0; h < 2; h++) {
            int r = row0 + m0w + mt * 16 + lr + 8 * h;
            if (r >= M) continue;
            float rs = g_rs[r];
            if (rs == 0.f) {
                #pragma unroll
                for (int nt = 0; nt < 7; nt++) {
                    int col = n0 + nt * 8 + 2 * lc;
                    if (col >= FDIM) continue;
                    *(float2*)(fout + (size_t)r * FDIM + col) = make_float2(0.f, 0.f);
                }
            } else {
                #pragma unroll
                for (int nt = 0; nt < 7; nt++) {
                    int col = n0 + nt * 8 + 2 * lc;
                    if (col >= FDIM) continue;
                    float v0 = acc[mt][nt][2 * h + 0];
                    float v1 = acc[mt][nt][2 * h + 1];
                    v0 = (v0 > 0.f) ? v0 : (expf(v0) - 1.f);
                    v1 = (v1 > 0.f) ? v1 : (expf(v1) - 1.f);
                    *(float2*)(fout + (size_t)r * FDIM + col) = make_float2(v0, v1);
                }
            }
        }
    }
}

// ---------------- phase 2: x-space role-split gather ----------------
__global__ __launch_bounds__(256) void gather_kernel(const float* __restrict__ x,
                                                     const float* __restrict__ emb1,
                                                     const float* __restrict__ emb2) {
    int t = threadIdx.x;
    int warp = t >> 5, lane = t & 31;
    int node = blockIdx.x * 4 + (warp >> 1);
    int role = warp & 1;
    if (node >= N_NODES) return;

    int beg = g_off[node];
    int end = g_off[node + 1];

    float4 a0 = make_float4(0, 0, 0, 0), a1 = a0;
    float rs = 0.f;

    for (int base = beg; base < end; base += 32) {
        int cnt = min(32, end - base);
        int4 rr = (lane < cnt) ? g_rec3[base + lane] : make_int4(0, 0, 0, 0);

        int j = 0;
        for (; j + 4 <= cnt; j += 4) {
            const float4* p[4];
            float e[4];
            #pragma unroll
            for (int k = 0; k < 4; k++) {
                int dstk = __shfl_sync(0xffffffffu, rr.x, j + k);
                int eidk = __shfl_sync(0xffffffffu, rr.y, j + k);
                e[k] = __int_as_float(__shfl_sync(0xffffffffu, rr.z, j + k));
                if (role == 0) {
                    p[k] = (eidk < E1C) ? (const float4*)emb1 + (size_t)eidk * 50
                                        : (const float4*)emb2 + (size_t)(eidk - E1C) * 50;
                } else {
                    p[k] = (const float4*)x + (size_t)dstk * 50;
                }
            }
            float4 v[4], u[4];
            #pragma unroll
            for (int k = 0; k < 4; k++) v[k] = p[k][lane];
            if (lane < 18) {
                #pragma unroll
                for (int k = 0; k < 4; k++) u[k] = p[k][32 + lane];
            }
            #pragma unroll
            for (int k = 0; k < 4; k++) {
                rs += e[k];
                a0.x += e[k] * v[k].x; a0.y += e[k] * v[k].y;
                a0.z += e[k] * v[k].z; a0.w += e[k] * v[k].w;
            }
            if (lane < 18) {
                #pragma unroll
                for (int k = 0; k < 4; k++) {
                    a1.x += e[k] * u[k].x; a1.y += e[k] * u[k].y;
                    a1.z += e[k] * u[k].z; a1.w += e[k] * u[k].w;
                }
            }
        }
        for (; j < cnt; j++) {
            int dst0 = __shfl_sync(0xffffffffu, rr.x, j);
            int eid0 = __shfl_sync(0xffffffffu, rr.y, j);
            float e0 = __int_as_float(__shfl_sync(0xffffffffu, rr.z, j));
            const float4* p0;
            if (role == 0) {
                p0 = (eid0 < E1C) ? (const float4*)emb1 + (size_t)eid0 * 50
                                  : (const float4*)emb2 + (size_t)(eid0 - E1C) * 50;
            } else {
                p0 = (const float4*)x + (size_t)dst0 * 50;
            }
            float4 v0 = p0[lane];
            rs += e0;
            a0.x += e0 * v0.x; a0.y += e0 * v0.y; a0.z += e0 * v0.z; a0.w += e0 * v0.w;
            if (lane < 18) {
                float4 u0 = p0[32 + lane];
                a1.x += e0 * u0.x; a1.y += e0 * u0.y; a1.z += e0 * u0.z; a1.w += e0 * u0.w;
            }
        }
    }

    float inv = (rs == 0.f) ? 0.f : 1.f / rs;
    a0.x *= inv; a0.y *= inv; a0.z *= inv; a0.w *= inv;
    a1.x *= inv; a1.y *= inv; a1.z *= inv; a1.w *= inv;

    int colbase = (role == 0) ? 200 : 100;
    unsigned h0, l0, h1, l1;
    split_pack2(a0.x, a0.y, h0, l0);
    split_pack2(a0.z, a0.w, h1, l1);
    size_t o = (size_t)node * KP_ROW + colbase + 2 * lane;
    *(uint2*)&g_aqh[o] = make_uint2(h0, h1);
    *(uint2*)&g_aql[o] = make_uint2(l0, l1);
    if (lane < 18) {
        split_pack2(a1.x, a1.y, h0, l0);
        split_pack2(a1.z, a1.w, h1, l1);
        size_t o2 = (size_t)node * KP_ROW + colbase + 64 + 2 * lane;
        *(uint2*)&g_aqh[o2] = make_uint2(h0, h1);
        *(uint2*)&g_aql[o2] = make_uint2(l0, l1);
    }
    if (role == 0 && lane == 0) g_rs[node] = rs;
}

// ---- streams/events created once at load time ----
struct GraphResources {
    cudaStream_t s1, s2;
    cudaEvent_t evStart, evPX, evCSR;
    GraphResources() {
        cudaStreamCreateWithFlags(&s1, cudaStreamNonBlocking);
        cudaStreamCreateWithFlags(&s2, cudaStreamNonBlocking);
        cudaEventCreateWithFlags(&evStart, cudaEventDisableTiming);
        cudaEventCreateWithFlags(&evPX, cudaEventDisableTiming);
        cudaEventCreateWithFlags(&evCSR, cudaEventDisableTiming);
    }
};
static GraphResources g_gr;

extern "C" void kernel_launch(void* const* d_in, const int* in_sizes, int n_in,
                              void* d_out, int out_size) {
    const float* x    = (const float*)d_in[0];
    const int*   edge = (const int*)  d_in[1];
    const float* ee1  = (const float*)d_in[2];
    const int*   edg2 = (const int*)  d_in[3];
    const float* ee2  = (const float*)d_in[4];
    const float* a    = (const float*)d_in[5];
    const float* a2   = (const float*)d_in[6];
    const float* mw   = (const float*)d_in[7];
    const float* mb   = (const float*)d_in[8];
    float* out = (float*)d_out;

    cudaFuncSetAttribute(tgemm_kernel, cudaFuncAttributeMaxDynamicSharedMemorySize, SMEM_BYTES);

    int ggrid = (N_NODES + BM - 1) / BM;
    cudaStream_t s0 = 0;

    cudaEventRecord(g_gr.evStart, s0);

    // s0: vw -> pvec -> score (shortest path to score)
    vw_kernel<<<1, 640, 0, s0>>>(a, a2, mw);
    pvec_kernel<<<N_NODES / 8, 256, 0, s0>>>(x);
    score_kernel<<<(E_TOT + 15) / 16, 256, 0, s0>>>(edge, ee1, edg2, ee2, mb);

    // s2: transpose (B planes) + pack_x — only needed by final GEMM
    cudaStreamWaitEvent(g_gr.s2, g_gr.evStart, 0);
    transpose_kernel<<<(300 * FDIM + 255) / 256, 256, 0, g_gr.s2>>>(a);
    pack_x_kernel<<<(N_NODES * 50 + 255) / 256, 256, 0, g_gr.s2>>>(x);
    cudaEventRecord(g_gr.evPX, g_gr.s2);

    // s1: CSR build
    cudaStreamWaitEvent(g_gr.s1, g_gr.evStart, 0);
    deg_kernel<<<(E_TOT + 255) / 256, 256, 0, g_gr.s1>>>(edge, edg2);
    scan_kernel<<<1, 1024, 0, g_gr.s1>>>();
    fill_kernel<<<(E_TOT + 255) / 256, 256, 0, g_gr.s1>>>(edge, edg2);
    cudaEventRecord(g_gr.evCSR, g_gr.s1);

    // s0: pack recs (needs score + CSR), then gather (no GEMM dependency)
    cudaStreamWaitEvent(s0, g_gr.evCSR, 0);
    pack_kernel<<<(E_TOT + 255) / 256, 256, 0, s0>>>();
    gather_kernel<<<(N_NODES + 3) / 4, 256, 0, s0>>>(x, ee1, ee2);

    // fused final GEMM (needs gather on s0 + transpose/pack_x)
    cudaStreamWaitEvent(s0, g_gr.evPX, 0);
    tgemm_kernel<<<ggrid, TG_THREADS, SMEM_BYTES, s0>>>(N_NODES, out);
}

// round 17
// speedup vs baseline: 1.2770x; 1.0328x over previous
#include <cuda_runtime.h>
#include <cuda_bf16.h>
#include <math.h>
#include <stdint.h>

#define N_NODES 50000
#define FDIM    200
#define E1C     400000
#define E2C     100000
#define E_TOT   500000
#define ALPHA   0.2f

// fused K=600 bf16 3x GEMM: BM=64, 256 threads, 2 CTAs/SM, double-buffered
#define BM 64
#define KP_TILE 20
#define NKB 15
#define KP_ROW 300
#define A_STRIDE 20
#define B_STRIDE 200
#define A_BUFU (BM * A_STRIDE)              // 1280 uints per plane
#define B_BUFU (KP_TILE * B_STRIDE + 64)
#define SMEM_UINTS (4 * A_BUFU + 4 * B_BUFU)
#define SMEM_BYTES (SMEM_UINTS * 4)
#define TG_THREADS 256

// ---- device scratch ----
__device__ float g_rs[N_NODES];
__device__ float g_p[4 * N_NODES];
__device__ float g_v[600];
__device__ float g_w[600];
__device__ unsigned g_bqh[300 * FDIM];
__device__ unsigned g_bql[300 * FDIM];
__device__ unsigned g_aqh[(size_t)N_NODES * KP_ROW];
__device__ unsigned g_aql[(size_t)N_NODES * KP_ROW];
__device__ float g_ee[E_TOT];
__device__ int  g_deg[N_NODES];
__device__ int  g_off[N_NODES + 1];
__device__ int  g_cur[N_NODES];
__device__ int2 g_rec[E_TOT];
__device__ int4 g_rec3[E_TOT];

__device__ __forceinline__ float dot4(float4 a, float4 b) {
    return a.x * b.x + a.y * b.y + a.z * b.z + a.w * b.w;
}

__device__ __forceinline__ float tanh_fast(float x) {
    float y;
    asm("tanh.approx.f32 %0, %1;" : "=f"(y) : "f"(x));
    return y;
}

__device__ __forceinline__ void split_pack2(float f0, float f1,
                                            unsigned& hi, unsigned& lo) {
    __nv_bfloat162 h = __float22bfloat162_rn(make_float2(f0, f1));
    hi = *reinterpret_cast<unsigned*>(&h);
    float l0 = f0 - __bfloat162float(h.x);
    float l1 = f1 - __bfloat162float(h.y);
    __nv_bfloat162 l = __float22bfloat162_rn(make_float2(l0, l1));
    lo = *reinterpret_cast<unsigned*>(&l);
}

__device__ __forceinline__ void mma_bf16_k16(float* c, const unsigned* a,
                                             unsigned b0, unsigned b1) {
    asm volatile("mma.sync.aligned.m16n8k16.row.col.f32.bf16.bf16.f32 "
                 "{%0,%1,%2,%3}, {%4,%5,%6,%7}, {%8,%9}, {%0,%1,%2,%3};"
                 : "+f"(c[0]), "+f"(c[1]), "+f"(c[2]), "+f"(c[3])
                 : "r"(a[0]), "r"(a[1]), "r"(a[2]), "r"(a[3]), "r"(b0), "r"(b1));
}

__device__ __forceinline__ void mma_bf16_k8(float* c, unsigned a0, unsigned a1,
                                            unsigned b0) {
    asm volatile("mma.sync.aligned.m16n8k8.row.col.f32.bf16.bf16.f32 "
                 "{%0,%1,%2,%3}, {%4,%5}, {%6}, {%0,%1,%2,%3};"
                 : "+f"(c[0]), "+f"(c[1]), "+f"(c[2]), "+f"(c[3])
                 : "r"(a0), "r"(a1), "r"(b0));
}

__device__ __forceinline__ void cp_async16(void* smem_dst, const void* gmem_src, bool pred) {
    uint32_t s = (uint32_t)__cvta_generic_to_shared(smem_dst);
    int sz = pred ? 16 : 0;
    asm volatile("cp.async.cg.shared.global [%0], [%1], 16, %2;"
                 :: "r"(s), "l"(gmem_src), "r"(sz));
}
__device__ __forceinline__ void cp_commit() {
    asm volatile("cp.async.commit_group;");
}
template<int N>
__device__ __forceinline__ void cp_wait() {
    asm volatile("cp.async.wait_group %0;" :: "n"(N));
}

// ---------------- CSR build ----------------
__global__ __launch_bounds__(256) void deg_kernel(const int* __restrict__ edge,
                                                  const int* __restrict__ edge2) {
    int e = blockIdx.x * blockDim.x + threadIdx.x;
    if (e >= E_TOT) return;
    int src = (e < E1C) ? edge[e] : edge2[e - E1C];
    atomicAdd(&g_deg[src], 1);
}

__global__ __launch_bounds__(1024) void scan_kernel() {
    __shared__ int warp_sums[32];
    __shared__ int s_total;
    __shared__ int s_run;
    int t = threadIdx.x;
    int lane = t & 31, wid = t >> 5;
    if (t == 0) s_run = 0;
    __syncthreads();
    for (int base = 0; base < N_NODES; base += 1024) {
        int idx = base + t;
        int v = 0;
        if (idx < N_NODES) {
            v = g_deg[idx];
            g_deg[idx] = 0;
        }
        int incl = v;
        #pragma unroll
        for (int d = 1; d < 32; d <<= 1) {
            int n = __shfl_up_sync(0xffffffffu, incl, d);
            if (lane >= d) incl += n;
        }
        if (lane == 31) warp_sums[wid] = incl;
        __syncthreads();
        if (wid == 0) {
            int ws = warp_sums[lane];
            int wincl = ws;
            #pragma unroll
            for (int d = 1; d < 32; d <<= 1) {
                int n = __shfl_up_sync(0xffffffffu, wincl, d);
                if (lane >= d) wincl += n;
            }
            warp_sums[lane] = wincl - ws;
            if (lane == 31) s_total = wincl;
        }
        __syncthreads();
        int excl = s_run + warp_sums[wid] + incl - v;
        if (idx < N_NODES) { g_off[idx] = excl; g_cur[idx] = excl; }
        __syncthreads();
        if (t == 0) s_run += s_total;
        __syncthreads();
    }
    if (t == 0) g_off[N_NODES] = s_run;
}

__global__ __launch_bounds__(256) void fill_kernel(const int* __restrict__ edge,
                                                   const int* __restrict__ edge2) {
    int e = blockIdx.x * blockDim.x + threadIdx.x;
    if (e >= E_TOT) return;
    int src, dst;
    if (e < E1C) { src = edge[e]; dst = edge[E1C + e]; }
    else         { src = edge2[e - E1C]; dst = edge2[E2C + (e - E1C)]; }
    int pos = atomicAdd(&g_cur[src], 1);
    g_rec[pos] = make_int2(dst, e);
}

__global__ __launch_bounds__(256) void pack_kernel() {
    int i = blockIdx.x * blockDim.x + threadIdx.x;
    if (i >= E_TOT) return;
    int2 r = g_rec[i];
    float e = g_ee[r.y];
    g_rec3[i] = make_int4(r.x, r.y, __float_as_int(e), 0);
}

// ---------------- weights prep ----------------
__global__ __launch_bounds__(256) void transpose_kernel(const float* __restrict__ a) {
    int i = blockIdx.x * blockDim.x + threadIdx.x;
    if (i >= 300 * FDIM) return;
    int jp = i / FDIM;
    int n  = i % FDIM;
    float f0 = a[n * 600 + 2 * jp];
    float f1 = a[n * 600 + 2 * jp + 1];
    unsigned hi, lo;
    split_pack2(f0, f1, hi, lo);
    g_bqh[i] = hi;
    g_bql[i] = lo;
}

__global__ __launch_bounds__(256) void pack_x_kernel(const float* __restrict__ x) {
    int i = blockIdx.x * blockDim.x + threadIdx.x;
    if (i >= N_NODES * 50) return;
    int m = i / 50, c = i % 50;
    float4 v = ((const float4*)x)[i];
    unsigned h0, l0, h1, l1;
    split_pack2(v.x, v.y, h0, l0);
    split_pack2(v.z, v.w, h1, l1);
    size_t o = (size_t)m * KP_ROW + 2 * c;
    *(uint2*)&g_aqh[o] = make_uint2(h0, h1);
    *(uint2*)&g_aql[o] = make_uint2(l0, l1);
}

__global__ __launch_bounds__(640) void vw_kernel(const float* __restrict__ a,
                                                 const float* __restrict__ a2,
                                                 const float* __restrict__ mw) {
    int j = threadIdx.x;
    if (j >= 600) return;
    float v = 0.f, w = 0.f;
    for (int o = 0; o < FDIM; o++) {
        float aj = a[o * 600 + j];
        v += aj * a2[o];
        w += aj * mw[o];
    }
    g_v[j] = v;
    g_w[j] = w;
}

__global__ __launch_bounds__(256) void pvec_kernel(const float* __restrict__ x) {
    __shared__ float4 sv[100];
    __shared__ float4 sw[100];
    int t = threadIdx.x;
    if (t < 100)       sv[t]       = ((const float4*)g_v)[t];
    else if (t < 200)  sw[t - 100] = ((const float4*)g_w)[t - 100];
    __syncthreads();

    int warp = t >> 5, lane = t & 31;
    int node = blockIdx.x * 8 + warp;
    if (node >= N_NODES) return;

    const float4* xr = (const float4*)x + (size_t)node * 50;
    float4 x0 = xr[lane];
    float4 x1 = (lane < 18) ? xr[32 + lane] : make_float4(0, 0, 0, 0);

    float p1  = dot4(x0, sv[lane])      + ((lane < 18) ? dot4(x1, sv[32 + lane]) : 0.f);
    float p2  = dot4(x0, sv[50 + lane]) + ((lane < 18) ? dot4(x1, sv[82 + lane]) : 0.f);
    float pm1 = dot4(x0, sw[lane])      + ((lane < 18) ? dot4(x1, sw[32 + lane]) : 0.f);
    float pm2 = dot4(x0, sw[50 + lane]) + ((lane < 18) ? dot4(x1, sw[82 + lane]) : 0.f);

    #pragma unroll
    for (int off = 16; off; off >>= 1) {
        p1  += __shfl_xor_sync(0xffffffffu, p1, off);
        p2  += __shfl_xor_sync(0xffffffffu, p2, off);
        pm1 += __shfl_xor_sync(0xffffffffu, pm1, off);
        pm2 += __shfl_xor_sync(0xffffffffu, pm2, off);
    }
    if (lane == 0) {
        g_p[node]               = p1;
        g_p[N_NODES + node]     = p2;
        g_p[2 * N_NODES + node] = pm1;
        g_p[3 * N_NODES + node] = pm2;
    }
}

// ---------------- phase 1: streaming edge scores (2 edges per warp) ----------------
__global__ __launch_bounds__(256) void score_kernel(const int* __restrict__ edge,
                                                    const float* __restrict__ emb1,
                                                    const int* __restrict__ edge2,
                                                    const float* __restrict__ emb2,
                                                    const float* __restrict__ mlp_b) {
    __shared__ float4 sv[50];
    __shared__ float4 sw[50];
    int t = threadIdx.x;
    if (t < 50)       sv[t]      = *(const float4*)&g_v[400 + t * 4];
    else if (t < 100) sw[t - 50] = *(const float4*)&g_w[400 + (t - 50) * 4];
    __syncthreads();

    int warp = t >> 5, lane = t & 31;
    int e0 = blockIdx.x * 16 + warp * 2;
    if (e0 >= E_TOT) return;
    bool hasB = (e0 + 1) < E_TOT;

    int srcA, dstA, srcB, dstB;
    const float4 *embA, *embB;
    if (e0 < E1C) {
        srcA = edge[e0]; dstA = edge[E1C + e0];
        embA = (const float4*)emb1 + (size_t)e0 * 50;
    } else {
        int r = e0 - E1C;
        srcA = edge2[r]; dstA = edge2[E2C + r];
        embA = (const float4*)emb2 + (size_t)r * 50;
    }
    int e1 = e0 + 1;
    if (hasB) {
        if (e1 < E1C) {
            srcB = edge[e1]; dstB = edge[E1C + e1];
            embB = (const float4*)emb1 + (size_t)e1 * 50;
        } else {
            int r = e1 - E1C;
            srcB = edge2[r]; dstB = edge2[E2C + r];
            embB = (const float4*)emb2 + (size_t)r * 50;
        }
    } else { srcB = srcA; dstB = dstA; embB = embA; }

    float4 svl = sv[lane];
    float4 swl = sw[lane];
    float4 a0 = embA[lane];
    float4 b0 = embB[lane];
    float4 a1 = (lane < 18) ? embA[32 + lane] : make_float4(0, 0, 0, 0);
    float4 b1 = (lane < 18) ? embB[32 + lane] : make_float4(0, 0, 0, 0);

    float q3A = dot4(a0, svl) + ((lane < 18) ? dot4(a1, sv[32 + lane]) : 0.f);
    float qmA = dot4(a0, swl) + ((lane < 18) ? dot4(a1, sw[32 + lane]) : 0.f);
    float q3B = dot4(b0, svl) + ((lane < 18) ? dot4(b1, sv[32 + lane]) : 0.f);
    float qmB = dot4(b0, swl) + ((lane < 18) ? dot4(b1, sw[32 + lane]) : 0.f);

    #pragma unroll
    for (int off = 16; off; off >>= 1) {
        q3A += __shfl_xor_sync(0xffffffffu, q3A, off);
        qmA += __shfl_xor_sync(0xffffffffu, qmA, off);
        q3B += __shfl_xor_sync(0xffffffffu, q3B, off);
        qmB += __shfl_xor_sync(0xffffffffu, qmB, off);
    }

    if (lane == 0) {
        float bias = mlp_b[0];
        float saA = g_p[srcA] + g_p[N_NODES + dstA] + q3A;
        float smA = g_p[2 * N_NODES + srcA] + g_p[3 * N_NODES + dstA] + qmA + bias;
        float lrA = (saA > 0.f) ? saA : ALPHA * saA;
        g_ee[e0] = __expf(-lrA * tanh_fast(smA) * (1.0f / (float)E_TOT));
        if (hasB) {
            float saB = g_p[srcB] + g_p[N_NODES + dstB] + q3B;
            float smB = g_p[2 * N_NODES + srcB] + g_p[3 * N_NODES + dstB] + qmB + bias;
            float lrB = (saB > 0.f) ? saB : ALPHA * saB;
            g_ee[e1] = __expf(-lrB * tanh_fast(smB) * (1.0f / (float)E_TOT));
        }
    }
}

// ---------------- fused K=600 GEMM: BM=64, 256 thr, 2 CTA/SM ----------------
__device__ __forceinline__ void stage_tile(unsigned* Ah, unsigned* Al,
                                           unsigned* Bh, unsigned* Bl,
                                           int M, int row0, int kb, int t) {
    int kp0 = kb * KP_TILE;
    // A: 64 rows x 5 float4 = 320 float4 per plane
    #pragma unroll
    for (int i = 0; i < 2; i++) {
        int idx = t + i * TG_THREADS;
        if (idx < 320) {
            int r = idx / 5, c4 = idx % 5;
            bool ok = (row0 + r) < M;
            size_t go = (size_t)(row0 + r) * KP_ROW + kp0 + c4 * 4;
            cp_async16(Ah + r * A_STRIDE + c4 * 4, g_aqh + go, ok);
            cp_async16(Al + r * A_STRIDE + c4 * 4, g_aql + go, ok);
        }
    }
    const unsigned* sH = g_bqh + (size_t)kp0 * FDIM;
    const unsigned* sL = g_bql + (size_t)kp0 * FDIM;
    #pragma unroll
    for (int i = 0; i < 4; i++) {
        int idx = t + i * TG_THREADS;
        if (idx < 1000) {
            int row = idx / 50, c4 = idx % 50;
            cp_async16(Bh + row * B_STRIDE + c4 * 4, sH + idx * 4, true);
            cp_async16(Bl + row * B_STRIDE + c4 * 4, sL + idx * 4, true);
        }
    }
}

__global__ void __launch_bounds__(TG_THREADS, 2)
tgemm_kernel(int M, float* __restrict__ fout) {
    extern __shared__ unsigned smu_[];
    unsigned* Ah[2] = { smu_, smu_ + A_BUFU };
    unsigned* Al[2] = { smu_ + 2 * A_BUFU, smu_ + 3 * A_BUFU };
    unsigned* bbase = smu_ + 4 * A_BUFU;
    unsigned* Bh[2] = { bbase, bbase + B_BUFU };
    unsigned* Bl[2] = { bbase + 2 * B_BUFU, bbase + 3 * B_BUFU };

    int row0 = blockIdx.x * BM;
    int t = threadIdx.x;
    int warp = t >> 5, lane = t & 31;
    int mg = warp >> 2;            // 0..1 -> 32 rows each
    int ng = warp & 3;             // 0..3 -> n0 = ng*56
    int n0 = ng * 56;
    int m0w = mg * 32;
    int lr = lane >> 2;
    int lc = lane & 3;

    float acc[2][7][4];
    #pragma unroll
    for (int a_ = 0; a_ < 2; a_++)
        #pragma unroll
        for (int b_ = 0; b_ < 7; b_++)
            #pragma unroll
            for (int c_ = 0; c_ < 4; c_++) acc[a_][b_][c_] = 0.f;

    stage_tile(Ah[0], Al[0], Bh[0], Bl[0], M, row0, 0, t);
    cp_commit();

    for (int kb = 0; kb < NKB; kb++) {
        int cur = kb & 1;
        if (kb + 1 < NKB) {
            stage_tile(Ah[cur ^ 1], Al[cur ^ 1], Bh[cur ^ 1], Bl[cur ^ 1],
                       M, row0, kb + 1, t);
            cp_commit();
            cp_wait<1>();
        } else {
            cp_wait<0>();
        }
        __syncthreads();

        const unsigned* Ach = Ah[cur];
        const unsigned* Acl = Al[cur];
        const unsigned* Bch = Bh[cur];
        const unsigned* Bcl = Bl[cur];

        #pragma unroll
        for (int st = 0; st < 2; st++) {
            int kpb = st * 8;
            unsigned ah[2][4], al[2][4];
            #pragma unroll
            for (int mt = 0; mt < 2; mt++) {
                int mrow = m0w + mt * 16 + lr;
                ah[mt][0] = Ach[mrow * A_STRIDE + kpb + lc];
                ah[mt][1] = Ach[(mrow + 8) * A_STRIDE + kpb + lc];
                ah[mt][2] = Ach[mrow * A_STRIDE + kpb + lc + 4];
                ah[mt][3] = Ach[(mrow + 8) * A_STRIDE + kpb + lc + 4];
                al[mt][0] = Acl[mrow * A_STRIDE + kpb + lc];
                al[mt][1] = Acl[(mrow + 8) * A_STRIDE + kpb + lc];
                al[mt][2] = Acl[mrow * A_STRIDE + kpb + lc + 4];
                al[mt][3] = Acl[(mrow + 8) * A_STRIDE + kpb + lc + 4];
            }
            #pragma unroll
            for (int nt = 0; nt < 7; nt++) {
                if (n0 + nt * 8 >= FDIM) continue;   // skip fully-OOB tiles
                int nc = n0 + nt * 8 + lr;
                unsigned bh0 = Bch[(kpb + lc) * B_STRIDE + nc];
                unsigned bh1 = Bch[(kpb + lc + 4) * B_STRIDE + nc];
                unsigned bl0 = Bcl[(kpb + lc) * B_STRIDE + nc];
                unsigned bl1 = Bcl[(kpb + lc + 4) * B_STRIDE + nc];
                #pragma unroll
                for (int mt = 0; mt < 2; mt++) {
                    mma_bf16_k16(acc[mt][nt], ah[mt], bh0, bh1);
                    mma_bf16_k16(acc[mt][nt], ah[mt], bl0, bl1);
                    mma_bf16_k16(acc[mt][nt], al[mt], bh0, bh1);
                }
            }
        }
        {
            unsigned ah8[2][2], al8[2][2];
            #pragma unroll
            for (int mt = 0; mt < 2; mt++) {
                int mrow = m0w + mt * 16 + lr;
                ah8[mt][0] = Ach[mrow * A_STRIDE + 16 + lc];
                ah8[mt][1] = Ach[(mrow + 8) * A_STRIDE + 16 + lc];
                al8[mt][0] = Acl[mrow * A_STRIDE + 16 + lc];
                al8[mt][1] = Acl[(mrow + 8) * A_STRIDE + 16 + lc];
            }
            #pragma unroll
            for (int nt = 0; nt < 7; nt++) {
                if (n0 + nt * 8 >= FDIM) continue;
                int nc = n0 + nt * 8 + lr;
                unsigned bh0 = Bch[(16 + lc) * B_STRIDE + nc];
                unsigned bl0 = Bcl[(16 + lc) * B_STRIDE + nc];
                #pragma unroll
                for (int mt = 0; mt < 2; mt++) {
                    mma_bf16_k8(acc[mt][nt], ah8[mt][0], ah8[mt][1], bh0);
                    mma_bf16_k8(acc[mt][nt], ah8[mt][0], ah8[mt][1], bl0);
                    mma_bf16_k8(acc[mt][nt], al8[mt][0], al8[mt][1], bh0);
                }
            }
        }
        __syncthreads();
    }

    // epilogue: out = rs==0 ? 0 : elu(acc)
    #pragma unroll
    for (int mt = 0; mt < 2; mt++) {
        #pragma unroll
        for (int h = 0; h < 2; h++) {
            int r = row0 + m0w + mt * 16 + lr + 8 * h;
            if (r >= M) continue;
            float rs = g_rs[r];
            if (rs == 0.f) {
                #pragma unroll
                for (int nt = 0; nt < 7; nt++) {
                    int col = n0 + nt * 8 + 2 * lc;
                    if (col >= FDIM) continue;
                    *(float2*)(fout + (size_t)r * FDIM + col) = make_float2(0.f, 0.f);
                }
            } else {
                #pragma unroll
                for (int nt = 0; nt < 7; nt++) {
                    int col = n0 + nt * 8 + 2 * lc;
                    if (col >= FDIM) continue;
                    float v0 = acc[mt][nt][2 * h + 0];
                    float v1 = acc[mt][nt][2 * h + 1];
                    v0 = (v0 > 0.f) ? v0 : (expf(v0) - 1.f);
                    v1 = (v1 > 0.f) ? v1 : (expf(v1) - 1.f);
                    *(float2*)(fout + (size_t)r * FDIM + col) = make_float2(v0, v1);
                }
            }
        }
    }
}

// ---------------- phase 2: x-space role-split gather ----------------
__global__ __launch_bounds__(256) void gather_kernel(const float* __restrict__ x,
                                                     const float* __restrict__ emb1,
                                                     const float* __restrict__ emb2) {
    int t = threadIdx.x;
    int warp = t >> 5, lane = t & 31;
    int node = blockIdx.x * 4 + (warp >> 1);
    int role = warp & 1;
    if (node >= N_NODES) return;

    int beg = g_off[node];
    int end = g_off[node + 1];

    float4 a0 = make_float4(0, 0, 0, 0), a1 = a0;
    float rs = 0.f;

    for (int base = beg; base < end; base += 32) {
        int cnt = min(32, end - base);
        int4 rr = (lane < cnt) ? g_rec3[base + lane] : make_int4(0, 0, 0, 0);

        int j = 0;
        for (; j + 4 <= cnt; j += 4) {
            const float4* p[4];
            float e[4];
            #pragma unroll
            for (int k = 0; k < 4; k++) {
                int dstk = __shfl_sync(0xffffffffu, rr.x, j + k);
                int eidk = __shfl_sync(0xffffffffu, rr.y, j + k);
                e[k] = __int_as_float(__shfl_sync(0xffffffffu, rr.z, j + k));
                if (role == 0) {
                    p[k] = (eidk < E1C) ? (const float4*)emb1 + (size_t)eidk * 50
                                        : (const float4*)emb2 + (size_t)(eidk - E1C) * 50;
                } else {
                    p[k] = (const float4*)x + (size_t)dstk * 50;
                }
            }
            float4 v[4], u[4];
            #pragma unroll
            for (int k = 0; k < 4; k++) v[k] = p[k][lane];
            if (lane < 18) {
                #pragma unroll
                for (int k = 0; k < 4; k++) u[k] = p[k][32 + lane];
            }
            #pragma unroll
            for (int k = 0; k < 4; k++) {
                rs += e[k];
                a0.x += e[k] * v[k].x; a0.y += e[k] * v[k].y;
                a0.z += e[k] * v[k].z; a0.w += e[k] * v[k].w;
            }
            if (lane < 18) {
                #pragma unroll
                for (int k = 0; k < 4; k++) {
                    a1.x += e[k] * u[k].x; a1.y += e[k] * u[k].y;
                    a1.z += e[k] * u[k].z; a1.w += e[k] * u[k].w;
                }
            }
        }
        for (; j < cnt; j++) {
            int dst0 = __shfl_sync(0xffffffffu, rr.x, j);
            int eid0 = __shfl_sync(0xffffffffu, rr.y, j);
            float e0 = __int_as_float(__shfl_sync(0xffffffffu, rr.z, j));
            const float4* p0;
            if (role == 0) {
                p0 = (eid0 < E1C) ? (const float4*)emb1 + (size_t)eid0 * 50
                                  : (const float4*)emb2 + (size_t)(eid0 - E1C) * 50;
            } else {
                p0 = (const float4*)x + (size_t)dst0 * 50;
            }
            float4 v0 = p0[lane];
            rs += e0;
            a0.x += e0 * v0.x; a0.y += e0 * v0.y; a0.z += e0 * v0.z; a0.w += e0 * v0.w;
            if (lane < 18) {
                float4 u0 = p0[32 + lane];
                a1.x += e0 * u0.x; a1.y += e0 * u0.y; a1.z += e0 * u0.z; a1.w += e0 * u0.w;
            }
        }
    }

    float inv = (rs == 0.f) ? 0.f : 1.f / rs;
    a0.x *= inv; a0.y *= inv; a0.z *= inv; a0.w *= inv;
    a1.x *= inv; a1.y *= inv; a1.z *= inv; a1.w *= inv;

    int colbase = (role == 0) ? 200 : 100;
    unsigned h0, l0, h1, l1;
    split_pack2(a0.x, a0.y, h0, l0);
    split_pack2(a0.z, a0.w, h1, l1);
    size_t o = (size_t)node * KP_ROW + colbase + 2 * lane;
    *(uint2*)&g_aqh[o] = make_uint2(h0, h1);
    *(uint2*)&g_aql[o] = make_uint2(l0, l1);
    if (lane < 18) {
        split_pack2(a1.x, a1.y, h0, l0);
        split_pack2(a1.z, a1.w, h1, l1);
        size_t o2 = (size_t)node * KP_ROW + colbase + 64 + 2 * lane;
        *(uint2*)&g_aqh[o2] = make_uint2(h0, h1);
        *(uint2*)&g_aql[o2] = make_uint2(l0, l1);
    }
    if (role == 0 && lane == 0) g_rs[node] = rs;
}

// ---- streams/events created once at load time ----
struct GraphResources {
    cudaStream_t s1, s2;
    cudaEvent_t evStart, evPX, evCSR;
    GraphResources() {
        cudaStreamCreateWithFlags(&s1, cudaStreamNonBlocking);
        cudaStreamCreateWithFlags(&s2, cudaStreamNonBlocking);
        cudaEventCreateWithFlags(&evStart, cudaEventDisableTiming);
        cudaEventCreateWithFlags(&evPX, cudaEventDisableTiming);
        cudaEventCreateWithFlags(&evCSR, cudaEventDisableTiming);
    }
};
static GraphResources g_gr;

extern "C" void kernel_launch(void* const* d_in, const int* in_sizes, int n_in,
                              void* d_out, int out_size) {
    const float* x    = (const float*)d_in[0];
    const int*   edge = (const int*)  d_in[1];
    const float* ee1  = (const float*)d_in[2];
    const int*   edg2 = (const int*)  d_in[3];
    const float* ee2  = (const float*)d_in[4];
    const float* a    = (const float*)d_in[5];
    const float* a2   = (const float*)d_in[6];
    const float* mw   = (const float*)d_in[7];
    const float* mb   = (const float*)d_in[8];
    float* out = (float*)d_out;

    cudaFuncSetAttribute(tgemm_kernel, cudaFuncAttributeMaxDynamicSharedMemorySize, SMEM_BYTES);

    int ggrid = (N_NODES + BM - 1) / BM;
    cudaStream_t s0 = 0;

    cudaEventRecord(g_gr.evStart, s0);

    // s0: vw -> pvec -> score
    vw_kernel<<<1, 640, 0, s0>>>(a, a2, mw);
    pvec_kernel<<<N_NODES / 8, 256, 0, s0>>>(x);
    score_kernel<<<(E_TOT + 15) / 16, 256, 0, s0>>>(edge, ee1, edg2, ee2, mb);

    // s2: transpose + pack_x (only needed by final GEMM)
    cudaStreamWaitEvent(g_gr.s2, g_gr.evStart, 0);
    transpose_kernel<<<(300 * FDIM + 255) / 256, 256, 0, g_gr.s2>>>(a);
    pack_x_kernel<<<(N_NODES * 50 + 255) / 256, 256, 0, g_gr.s2>>>(x);
    cudaEventRecord(g_gr.evPX, g_gr.s2);

    // s1: CSR build
    cudaStreamWaitEvent(g_gr.s1, g_gr.evStart, 0);
    deg_kernel<<<(E_TOT + 255) / 256, 256, 0, g_gr.s1>>>(edge, edg2);
    scan_kernel<<<1, 1024, 0, g_gr.s1>>>();
    fill_kernel<<<(E_TOT + 255) / 256, 256, 0, g_gr.s1>>>(edge, edg2);
    cudaEventRecord(g_gr.evCSR, g_gr.s1);

    // s0: pack recs (needs score + CSR), then gather
    cudaStreamWaitEvent(s0, g_gr.evCSR, 0);
    pack_kernel<<<(E_TOT + 255) / 256, 256, 0, s0>>>();
    gather_kernel<<<(N_NODES + 3) / 4, 256, 0, s0>>>(x, ee1, ee2);

    // fused final GEMM
    cudaStreamWaitEvent(s0, g_gr.evPX, 0);
    tgemm_kernel<<<ggrid, TG_THREADS, SMEM_BYTES, s0>>>(N_NODES, out);
}